// round 1
// baseline (speedup 1.0000x reference)
#include <cuda_runtime.h>
#include <cuda_bf16.h>
#include <cstdint>

// Problem constants
#define NB 16
#define NT 9
#define NYX 256
#define SP 65536            // 256*256
#define C1 10
#define C2 20
#define C3 54

// Output layout (f32, concatenated tuple)
#define OFF_XOUT 0
#define OFF_KAP  16
#define OFF_M    9437200            // 16 + 16*9*65536
#define OFF_H    28311568           // OFF_M + 16*18*65536

// Scratch (static device globals; no runtime allocation allowed)
__device__ float g_p1[NB * C1 * SP];
__device__ float g_p2[NB * C2 * SP];
__device__ float g_p3[NB * C3 * SP];
__device__ float g_xg[NB * NT * SP];
__device__ float g_w [NB * NT * SP];
__device__ float g_v [NB * NT * SP];
__device__ float g_part[NB * 160];

__device__ __forceinline__ float sp10(float x) {
    // softplus(10x)/10 = (max(z,0) + log1p(exp(-|z|))) / 10, z = 10x
    float z = 10.0f * x;
    return (fmaxf(z, 0.0f) + log1pf(expf(-fabsf(z)))) * 0.1f;
}

// ---------------------------------------------------------------------------
// 3x3 SAME conv (cross-correlation, NCHW/OIHW).
// block (32, CO_CHUNK); each thread: 1 cout, 4 rows x 8 cols.
// grid  (ceil(COUT/CO_CHUNK), 64, NB)
// Dynamic shared: in tile CIN*6*264 floats, then weights CO_CHUNK*CIN*9.
// ---------------------------------------------------------------------------
template <int CIN, bool RELU_IN>
__global__ void conv3x3_k(const float* __restrict__ in,
                          const float* __restrict__ wts,
                          float* __restrict__ out, int COUT) {
    extern __shared__ float sh[];
    const int RS = 264;                        // padded row stride
    float* in_sh = sh;
    float* w_sh  = sh + CIN * 6 * RS;

    const int b = blockIdx.z;
    const int y0 = blockIdx.y * 4;
    const int chunk = blockIdx.x;
    const int nth = blockDim.x * blockDim.y;
    const int tid = threadIdx.y * 32 + threadIdx.x;

    // load input tile (6 rows with halo, 258 cols with halo), zero padded
    const float* inb = in + (size_t)b * CIN * SP;
    for (int idx = tid; idx < CIN * 6 * 258; idx += nth) {
        int col = idx % 258;
        int tmp = idx / 258;
        int row = tmp % 6;
        int cin = tmp / 6;
        int gy = y0 - 1 + row;
        int gx = col - 1;
        float v = 0.0f;
        if (gy >= 0 && gy < NYX && gx >= 0 && gx < NYX) {
            v = inb[cin * SP + gy * NYX + gx];
            if (RELU_IN) v = fmaxf(v, 0.0f);
        }
        in_sh[(cin * 6 + row) * RS + col] = v;
    }
    // load this chunk's weights
    const int wcnt = blockDim.y * CIN * 9;
    for (int idx = tid; idx < wcnt; idx += nth) {
        int co = idx / (CIN * 9);
        int g = chunk * blockDim.y + co;
        w_sh[idx] = (g < COUT) ? wts[(size_t)g * CIN * 9 + idx % (CIN * 9)] : 0.0f;
    }
    __syncthreads();

    const int co = chunk * blockDim.y + threadIdx.y;
    float acc[4][8];
#pragma unroll
    for (int r = 0; r < 4; r++)
#pragma unroll
        for (int p = 0; p < 8; p++) acc[r][p] = 0.0f;

    const float* wrow = w_sh + threadIdx.y * CIN * 9;
    const int xbase = threadIdx.x * 8;

    for (int cin = 0; cin < CIN; ++cin) {
#pragma unroll
        for (int ky = 0; ky < 3; ++ky) {
            float w0 = wrow[cin * 9 + ky * 3 + 0];
            float w1 = wrow[cin * 9 + ky * 3 + 1];
            float w2 = wrow[cin * 9 + ky * 3 + 2];
#pragma unroll
            for (int r = 0; r < 4; ++r) {
                const float* rp = &in_sh[(cin * 6 + r + ky) * RS + xbase];
                float t[10];
#pragma unroll
                for (int q = 0; q < 10; q++) t[q] = rp[q];
#pragma unroll
                for (int p = 0; p < 8; p++)
                    acc[r][p] += t[p] * w0 + t[p + 1] * w1 + t[p + 2] * w2;
            }
        }
    }

    if (co < COUT) {
        float* ob = out + ((size_t)b * COUT + co) * SP + (size_t)y0 * NYX + xbase;
#pragma unroll
        for (int r = 0; r < 4; ++r) {
            float4 v0 = make_float4(acc[r][0], acc[r][1], acc[r][2], acc[r][3]);
            float4 v1 = make_float4(acc[r][4], acc[r][5], acc[r][6], acc[r][7]);
            reinterpret_cast<float4*>(ob + (size_t)r * NYX)[0] = v0;
            reinterpret_cast<float4*>(ob + (size_t)r * NYX)[1] = v1;
        }
    }
}

// ---------------------------------------------------------------------------
// kappa_r (softplus10 of ch 0..8) and m_r (copy ch 9..26), vectorized float4.
// ---------------------------------------------------------------------------
__global__ void epiA_k(float* __restrict__ out) {
    size_t i = (size_t)blockIdx.x * blockDim.x + threadIdx.x;   // float4 idx
    const size_t total = (size_t)NB * 27 * SP / 4;
    if (i >= total) return;
    size_t e = i * 4;
    int s  = (int)(e & (SP - 1));
    int ch = (int)((e >> 16) % 27);
    int b  = (int)(e / ((size_t)SP * 27));
    float4 v = *reinterpret_cast<const float4*>(g_p3 + ((size_t)b * C3 + ch) * SP + s);
    size_t dst;
    if (ch < 9) {
        v.x = sp10(v.x); v.y = sp10(v.y); v.z = sp10(v.z); v.w = sp10(v.w);
        dst = OFF_KAP + ((size_t)b * 9 + ch) * SP + s;
    } else {
        dst = OFF_M + ((size_t)b * 18 + (ch - 9)) * SP + s;
    }
    *reinterpret_cast<float4*>(out + dst) = v;
}

// ---------------------------------------------------------------------------
// H_r[b,i,j,y,x,t] transpose-write. One thread per (b, s=y*256+x).
// ---------------------------------------------------------------------------
__global__ void epiH_k(float* __restrict__ out) {
    int gid = blockIdx.x * blockDim.x + threadIdx.x;   // 0 .. NB*SP-1
    int b = gid >> 16;
    int s = gid & (SP - 1);
    const float* pb = g_p3 + (size_t)b * C3 * SP + s;
    float gm[NT], vx[NT], vy[NT];
#pragma unroll
    for (int t = 0; t < NT; t++) {
        gm[t] = sp10(pb[(size_t)(27 + t) * SP]);
        vx[t] = pb[(size_t)(36 + t) * SP];
        vy[t] = pb[(size_t)(45 + t) * SP];
    }
    const size_t PLANE = (size_t)SP * NT;   // 589824
    size_t base = OFF_H + (size_t)b * 4 * PLANE + (size_t)s * NT;
#pragma unroll
    for (int t = 0; t < NT; t++) out[base + t] = gm[t] + vx[t] * vx[t];
#pragma unroll
    for (int t = 0; t < NT; t++) {
        float xy = vx[t] * vy[t];
        out[base + PLANE + t]     = xy;
        out[base + 2 * PLANE + t] = xy;
    }
#pragma unroll
    for (int t = 0; t < NT; t++) out[base + 3 * PLANE + t] = gm[t] + vy[t] * vy[t];
}

// ---------------------------------------------------------------------------
// xg = spatial transpose of x, per (b,t) plane.
// ---------------------------------------------------------------------------
__global__ void transpose_k(const float* __restrict__ x) {
    __shared__ float tile[32][33];
    int b = blockIdx.z / NT, t = blockIdx.z % NT;
    const float* xb = x + ((size_t)b * NT + t) * SP;
    float* og = g_xg + ((size_t)b * NT + t) * SP;
    int Y0 = blockIdx.y * 32, X0 = blockIdx.x * 32;
#pragma unroll
    for (int k = 0; k < 4; k++) {
        int row = threadIdx.y + k * 8;
        tile[row][threadIdx.x] = xb[(size_t)(Y0 + row) * NYX + X0 + threadIdx.x];
    }
    __syncthreads();
#pragma unroll
    for (int k = 0; k < 4; k++) {
        int row = threadIdx.y + k * 8;
        og[(size_t)(X0 + row) * NYX + Y0 + threadIdx.x] = tile[threadIdx.x][row];
    }
}

// ---------------------------------------------------------------------------
// M(u) = u + kap^2 u + m1 dx + m2 dy - (h11 dxx + 2 vx vy dxy + h22 dyy)
// Grid fields gathered from g_p3 (h's identity-mapped, kap/m scrambled).
// block (32,8), grid (8,32, NB*NT).
// ---------------------------------------------------------------------------
__global__ void applyM_k(const float* __restrict__ u, float* __restrict__ og) {
    __shared__ float tile[10][36];
    int b = blockIdx.z / NT, t = blockIdx.z % NT;
    int A0 = blockIdx.y * 8, C0 = blockIdx.x * 32;
    const float* ub = u + ((size_t)b * NT + t) * SP;
    int tid = threadIdx.y * 32 + threadIdx.x;
    for (int i = tid; i < 10 * 34; i += 256) {
        int rr = i / 34, cc = i % 34;
        int A = A0 - 1 + rr, C = C0 - 1 + cc;
        tile[rr][cc] = (A >= 0 && A < NYX && C >= 0 && C < NYX)
                       ? ub[(size_t)A * NYX + C] : 0.0f;
    }
    __syncthreads();
    int a = threadIdx.y, c = threadIdx.x;
    float u0 = tile[a + 1][c + 1];
    float xp = tile[a + 2][c + 1], xm = tile[a][c + 1];
    float yp = tile[a + 1][c + 2], ym = tile[a + 1][c];
    float pp = tile[a + 2][c + 2], pm = tile[a + 2][c];
    float mp = tile[a][c + 2],     mm = tile[a][c];
    float dx  = 0.5f * (xp - xm);
    float dy  = 0.5f * (yp - ym);
    float dxx = xp - 2.0f * u0 + xm;
    float dyy = yp - 2.0f * u0 + ym;
    float dxy = 0.25f * (pp - pm - mp + mm);

    int A = A0 + a, C = C0 + c;
    int s = A * NYX + C;
    const float* pb = g_p3 + (size_t)b * C3 * SP;
    float gm = sp10(pb[(size_t)(27 + t) * SP + s]);
    float vx = pb[(size_t)(36 + t) * SP + s];
    float vy = pb[(size_t)(45 + t) * SP + s];
    int L = s * NT + t;
    int tt  = L >> 16;
    int rem = L & (SP - 1);
    float kap = sp10(pb[(size_t)tt * SP + rem]);
    float m1  = pb[(size_t)(9 + tt) * SP + rem];
    float m2  = pb[(size_t)(18 + tt) * SP + rem];

    float r = u0 + kap * kap * u0 + m1 * dx + m2 * dy
            - ((gm + vx * vx) * dxx + 2.0f * vx * vy * dxy + (gm + vy * vy) * dyy);
    og[((size_t)b * NT + t) * SP + s] = r;
}

// ---------------------------------------------------------------------------
// qx + deterministic reduction (two stages, fixed order).
// stage1 grid: (144, NB); 4096 elems per block.
// ---------------------------------------------------------------------------
__global__ void qx_reduce_k() {
    __shared__ float sm[256];
    int b = blockIdx.y;
    size_t base = (size_t)blockIdx.x * 4096;
    const float* xb = g_xg + (size_t)b * NT * SP;
    const float* wb = g_w  + (size_t)b * NT * SP;
    const float* vb = g_v  + (size_t)b * NT * SP;
    float sum = 0.0f;
    for (int i = threadIdx.x; i < 4096; i += 256) {
        size_t e = base + i;
        int t = (int)(e >> 16);
        int s = (int)(e & (SP - 1));
        float q;
        if (t == 0)       q = vb[s] - wb[SP + s];
        else if (t == 8)  q = -wb[7 * SP + s] + vb[8 * (size_t)SP + s];
        else              q = -wb[(size_t)(t - 1) * SP + s] + vb[e] + xb[e]
                              - wb[(size_t)(t + 1) * SP + s];
        sum += xb[e] * q;
    }
    sm[threadIdx.x] = sum;
    __syncthreads();
    for (int st = 128; st > 0; st >>= 1) {
        if (threadIdx.x < st) sm[threadIdx.x] += sm[threadIdx.x + st];
        __syncthreads();
    }
    if (threadIdx.x == 0) g_part[b * 160 + blockIdx.x] = sm[0];
}

__global__ void final_reduce_k(float* __restrict__ out) {
    int b = threadIdx.x;
    if (b < NB) {
        float s = 0.0f;
        for (int i = 0; i < 144; i++) s += g_part[b * 160 + i];
        out[OFF_XOUT + b] = s;
    }
}

// ---------------------------------------------------------------------------
extern "C" void kernel_launch(void* const* d_in, const int* in_sizes, int n_in,
                              void* d_out, int out_size) {
    const float* x  = (const float*)d_in[0];
    const float* w1 = (const float*)d_in[4];
    const float* w2 = (const float*)d_in[5];
    const float* w3 = (const float*)d_in[6];
    float* out = (float*)d_out;

    float *p1, *p2, *p3, *xg, *wg, *vg;
    cudaGetSymbolAddress((void**)&p1, g_p1);
    cudaGetSymbolAddress((void**)&p2, g_p2);
    cudaGetSymbolAddress((void**)&p3, g_p3);
    cudaGetSymbolAddress((void**)&xg, g_xg);
    cudaGetSymbolAddress((void**)&wg, g_w);
    cudaGetSymbolAddress((void**)&vg, g_v);

    const int RS = 264;
    const int smem1 = (9  * 6 * RS + 10 * 9  * 9) * 4;   // 60264
    const int smem2 = (10 * 6 * RS + 10 * 10 * 9) * 4;   // 66960
    const int smem3 = (20 * 6 * RS + 14 * 20 * 9) * 4;   // 136800
    cudaFuncSetAttribute(conv3x3_k<9,  true >, cudaFuncAttributeMaxDynamicSharedMemorySize, smem1);
    cudaFuncSetAttribute(conv3x3_k<10, true >, cudaFuncAttributeMaxDynamicSharedMemorySize, smem2);
    cudaFuncSetAttribute(conv3x3_k<20, false>, cudaFuncAttributeMaxDynamicSharedMemorySize, smem3);

    // 3 conv layers (relu fused into input of conv1 and conv2)
    conv3x3_k<9,  true ><<<dim3(1, 64, NB), dim3(32, 10), smem1>>>(x,  w1, p1, C1);
    conv3x3_k<10, true ><<<dim3(2, 64, NB), dim3(32, 10), smem2>>>(p1, w2, p2, C2);
    conv3x3_k<20, false><<<dim3(4, 64, NB), dim3(32, 14), smem3>>>(p2, w3, p3, C3);

    // outputs: kappa_r + m_r, H_r
    epiA_k<<<(NB * 27 * SP / 4 + 255) / 256, 256>>>(out);
    epiH_k<<<(NB * SP) / 256, 256>>>(out);

    // PDE pipeline: xg = x^T ; w = M(xg) ; v = M(w) ; x_out reduction
    transpose_k<<<dim3(8, 8, NB * NT), dim3(32, 8)>>>(x);
    applyM_k<<<dim3(8, 32, NB * NT), dim3(32, 8)>>>(xg, wg);
    applyM_k<<<dim3(8, 32, NB * NT), dim3(32, 8)>>>(wg, vg);
    qx_reduce_k<<<dim3(144, NB), 256>>>();
    final_reduce_k<<<1, 32>>>(out);
}

// round 2
// speedup vs baseline: 1.0075x; 1.0075x over previous
#include <cuda_runtime.h>
#include <cuda_bf16.h>
#include <cstdint>

// Problem constants
#define NB 16
#define NT 9
#define NYX 256
#define SP 65536            // 256*256
#define C1 10
#define C2 20
#define C3 54

// Output layout (f32, concatenated tuple)
#define OFF_XOUT 0
#define OFF_KAP  16
#define OFF_M    9437200            // 16 + 16*9*65536
#define OFF_H    28311568           // OFF_M + 16*18*65536

typedef unsigned long long u64;

// Scratch (static device globals; no runtime allocation allowed)
__device__ float g_p1[NB * C1 * SP];
__device__ float g_p2[NB * C2 * SP];
__device__ float g_p3[NB * C3 * SP];
__device__ float g_xg[NB * NT * SP];
__device__ float g_w [NB * NT * SP];
__device__ float g_v [NB * NT * SP];
// precomputed coefficient grids, plane layout (b, t, s)
__device__ float g_kg [NB * NT * SP];
__device__ float g_m1 [NB * NT * SP];
__device__ float g_m2 [NB * NT * SP];
__device__ float g_h11[NB * NT * SP];
__device__ float g_hxy[NB * NT * SP];
__device__ float g_h22[NB * NT * SP];
__device__ float g_part[NB * 160];

__device__ __forceinline__ float sp10(float x) {
    float z = 10.0f * x;
    return (fmaxf(z, 0.0f) + log1pf(expf(-fabsf(z)))) * 0.1f;
}

// packed f32x2 helpers (Blackwell-only packed fp32 pipe; 2x FFMA throughput)
__device__ __forceinline__ u64 pk2(float lo, float hi) {
    u64 r; asm("mov.b64 %0, {%1, %2};" : "=l"(r) : "f"(lo), "f"(hi)); return r;
}
__device__ __forceinline__ float2 upk(u64 v) {
    float2 r; asm("mov.b64 {%0, %1}, %2;" : "=f"(r.x), "=f"(r.y) : "l"(v)); return r;
}
__device__ __forceinline__ void fma2(u64& d, u64 a, u64 b) {
    asm("fma.rn.f32x2 %0, %1, %2, %0;" : "+l"(d) : "l"(a), "l"(b));
}

// ---------------------------------------------------------------------------
// 3x3 SAME conv (cross-correlation, NCHW/OIHW) using packed f32x2 FMA.
// block (32, CO_CHUNK); each thread: 1 cout, 4 rows x 4 output-pairs (8 cols).
// grid  (ceil(COUT/CO_CHUNK), 64, NB)
// ---------------------------------------------------------------------------
template <int CIN, bool RELU_IN>
__global__ void conv3x3_k(const float* __restrict__ in,
                          const float* __restrict__ wts,
                          float* __restrict__ out, int COUT) {
    extern __shared__ float sh[];
    const int RS = 264;
    float* in_sh = sh;
    float* w_sh  = sh + CIN * 6 * RS;

    const int b = blockIdx.z;
    const int y0 = blockIdx.y * 4;
    const int chunk = blockIdx.x;
    const int nth = blockDim.x * blockDim.y;
    const int tid = threadIdx.y * 32 + threadIdx.x;

    const float* inb = in + (size_t)b * CIN * SP;
    for (int idx = tid; idx < CIN * 6 * 258; idx += nth) {
        int col = idx % 258;
        int tmp = idx / 258;
        int row = tmp % 6;
        int cin = tmp / 6;
        int gy = y0 - 1 + row;
        int gx = col - 1;
        float v = 0.0f;
        if (gy >= 0 && gy < NYX && gx >= 0 && gx < NYX) {
            v = inb[cin * SP + gy * NYX + gx];
            if (RELU_IN) v = fmaxf(v, 0.0f);
        }
        in_sh[(cin * 6 + row) * RS + col] = v;
    }
    const int wcnt = blockDim.y * CIN * 9;
    for (int idx = tid; idx < wcnt; idx += nth) {
        int co = idx / (CIN * 9);
        int g = chunk * blockDim.y + co;
        w_sh[idx] = (g < COUT) ? wts[(size_t)g * CIN * 9 + idx % (CIN * 9)] : 0.0f;
    }
    __syncthreads();

    const int co = chunk * blockDim.y + threadIdx.y;
    u64 acc[4][4];
#pragma unroll
    for (int r = 0; r < 4; r++)
#pragma unroll
        for (int q = 0; q < 4; q++) acc[r][q] = 0ull;

    const float* wrow = w_sh + threadIdx.y * CIN * 9;
    const int xbase = threadIdx.x * 8;

    for (int cin = 0; cin < CIN; ++cin) {
        u64 W[3][3];
#pragma unroll
        for (int ky = 0; ky < 3; ++ky)
#pragma unroll
            for (int j = 0; j < 3; ++j) {
                float w = wrow[cin * 9 + ky * 3 + j];
                W[ky][j] = pk2(w, w);
            }
        const float* base = &in_sh[cin * 6 * RS + xbase];
#pragma unroll
        for (int sr = 0; sr < 6; ++sr) {
            const float* rp = base + sr * RS;
            float t[10];
#pragma unroll
            for (int q = 0; q < 10; q++) t[q] = rp[q];
            u64 P0 = pk2(t[0], t[1]), P1 = pk2(t[2], t[3]),
                P2 = pk2(t[4], t[5]), P3 = pk2(t[6], t[7]), P4 = pk2(t[8], t[9]);
            u64 S1 = pk2(t[1], t[2]), S3 = pk2(t[3], t[4]),
                S5 = pk2(t[5], t[6]), S7 = pk2(t[7], t[8]);
#pragma unroll
            for (int ky = 0; ky < 3; ++ky) {
                int r = sr - ky;
                if (r >= 0 && r < 4) {
                    fma2(acc[r][0], P0, W[ky][0]); fma2(acc[r][0], S1, W[ky][1]); fma2(acc[r][0], P1, W[ky][2]);
                    fma2(acc[r][1], P1, W[ky][0]); fma2(acc[r][1], S3, W[ky][1]); fma2(acc[r][1], P2, W[ky][2]);
                    fma2(acc[r][2], P2, W[ky][0]); fma2(acc[r][2], S5, W[ky][1]); fma2(acc[r][2], P3, W[ky][2]);
                    fma2(acc[r][3], P3, W[ky][0]); fma2(acc[r][3], S7, W[ky][1]); fma2(acc[r][3], P4, W[ky][2]);
                }
            }
        }
    }

    if (co < COUT) {
        float* ob = out + ((size_t)b * COUT + co) * SP + (size_t)y0 * NYX + xbase;
#pragma unroll
        for (int r = 0; r < 4; ++r) {
            float2 o0 = upk(acc[r][0]), o1 = upk(acc[r][1]),
                   o2 = upk(acc[r][2]), o3 = upk(acc[r][3]);
            float4 v0 = make_float4(o0.x, o0.y, o1.x, o1.y);
            float4 v1 = make_float4(o2.x, o2.y, o3.x, o3.y);
            reinterpret_cast<float4*>(ob + (size_t)r * NYX)[0] = v0;
            reinterpret_cast<float4*>(ob + (size_t)r * NYX)[1] = v1;
        }
    }
}

// ---------------------------------------------------------------------------
// kappa_r (softplus10 of ch 0..8) and m_r (copy ch 9..26), vectorized float4.
// ---------------------------------------------------------------------------
__global__ void epiA_k(float* __restrict__ out) {
    size_t i = (size_t)blockIdx.x * blockDim.x + threadIdx.x;
    const size_t total = (size_t)NB * 27 * SP / 4;
    if (i >= total) return;
    size_t e = i * 4;
    int s  = (int)(e & (SP - 1));
    int ch = (int)((e >> 16) % 27);
    int b  = (int)(e / ((size_t)SP * 27));
    float4 v = *reinterpret_cast<const float4*>(g_p3 + ((size_t)b * C3 + ch) * SP + s);
    size_t dst;
    if (ch < 9) {
        v.x = sp10(v.x); v.y = sp10(v.y); v.z = sp10(v.z); v.w = sp10(v.w);
        dst = OFF_KAP + ((size_t)b * 9 + ch) * SP + s;
    } else {
        dst = OFF_M + ((size_t)b * 18 + (ch - 9)) * SP + s;
    }
    *reinterpret_cast<float4*>(out + dst) = v;
}

// ---------------------------------------------------------------------------
// H_r[b,i,j,y,x,t] transpose-write + h11/hxy/h22 plane grids (coalesced).
// ---------------------------------------------------------------------------
__global__ void epiH_k(float* __restrict__ out) {
    int gid = blockIdx.x * blockDim.x + threadIdx.x;
    int b = gid >> 16;
    int s = gid & (SP - 1);
    const float* pb = g_p3 + (size_t)b * C3 * SP + s;
    float gm[NT], vx[NT], vy[NT];
#pragma unroll
    for (int t = 0; t < NT; t++) {
        gm[t] = sp10(pb[(size_t)(27 + t) * SP]);
        vx[t] = pb[(size_t)(36 + t) * SP];
        vy[t] = pb[(size_t)(45 + t) * SP];
    }
    const size_t PLANE = (size_t)SP * NT;
    size_t base = OFF_H + (size_t)b * 4 * PLANE + (size_t)s * NT;
    size_t pb2 = (size_t)b * NT * SP + s;
#pragma unroll
    for (int t = 0; t < NT; t++) {
        float h11 = gm[t] + vx[t] * vx[t];
        out[base + t] = h11;
        g_h11[pb2 + (size_t)t * SP] = h11;
    }
#pragma unroll
    for (int t = 0; t < NT; t++) {
        float xy = vx[t] * vy[t];
        out[base + PLANE + t]     = xy;
        out[base + 2 * PLANE + t] = xy;
        g_hxy[pb2 + (size_t)t * SP] = xy;
    }
#pragma unroll
    for (int t = 0; t < NT; t++) {
        float h22 = gm[t] + vy[t] * vy[t];
        out[base + 3 * PLANE + t] = h22;
        g_h22[pb2 + (size_t)t * SP] = h22;
    }
}

// ---------------------------------------------------------------------------
// One-shot scramble: kg/m1/m2 plane grids (gather reads, coalesced writes).
// ---------------------------------------------------------------------------
__global__ void scramble_k() {
    int gid = blockIdx.x * blockDim.x + threadIdx.x;   // (b*9+t)*SP + s
    int s  = gid & (SP - 1);
    int bt = gid >> 16;
    int t = bt % NT, b = bt / NT;
    int L = s * NT + t;
    int tt  = L >> 16;
    int rem = L & (SP - 1);
    const float* pb = g_p3 + (size_t)b * C3 * SP;
    g_kg[gid] = sp10(pb[(size_t)tt * SP + rem]);
    g_m1[gid] = pb[(size_t)(9 + tt) * SP + rem];
    g_m2[gid] = pb[(size_t)(18 + tt) * SP + rem];
}

// ---------------------------------------------------------------------------
// xg = spatial transpose of x, per (b,t) plane.
// ---------------------------------------------------------------------------
__global__ void transpose_k(const float* __restrict__ x) {
    __shared__ float tile[32][33];
    int b = blockIdx.z / NT, t = blockIdx.z % NT;
    const float* xb = x + ((size_t)b * NT + t) * SP;
    float* og = g_xg + ((size_t)b * NT + t) * SP;
    int Y0 = blockIdx.y * 32, X0 = blockIdx.x * 32;
#pragma unroll
    for (int k = 0; k < 4; k++) {
        int row = threadIdx.y + k * 8;
        tile[row][threadIdx.x] = xb[(size_t)(Y0 + row) * NYX + X0 + threadIdx.x];
    }
    __syncthreads();
#pragma unroll
    for (int k = 0; k < 4; k++) {
        int row = threadIdx.y + k * 8;
        og[(size_t)(X0 + row) * NYX + Y0 + threadIdx.x] = tile[threadIdx.x][row];
    }
}

// ---------------------------------------------------------------------------
// M(u): all coefficient grids now coalesced plane reads.
// ---------------------------------------------------------------------------
__global__ void applyM_k(const float* __restrict__ u, float* __restrict__ og) {
    __shared__ float tile[10][36];
    int bt = blockIdx.z;
    int A0 = blockIdx.y * 8, C0 = blockIdx.x * 32;
    const float* ub = u + (size_t)bt * SP;
    int tid = threadIdx.y * 32 + threadIdx.x;
    for (int i = tid; i < 10 * 34; i += 256) {
        int rr = i / 34, cc = i % 34;
        int A = A0 - 1 + rr, C = C0 - 1 + cc;
        tile[rr][cc] = (A >= 0 && A < NYX && C >= 0 && C < NYX)
                       ? ub[(size_t)A * NYX + C] : 0.0f;
    }
    __syncthreads();
    int a = threadIdx.y, c = threadIdx.x;
    float u0 = tile[a + 1][c + 1];
    float xp = tile[a + 2][c + 1], xm = tile[a][c + 1];
    float yp = tile[a + 1][c + 2], ym = tile[a + 1][c];
    float pp = tile[a + 2][c + 2], pm = tile[a + 2][c];
    float mp = tile[a][c + 2],     mm = tile[a][c];
    float dx  = 0.5f * (xp - xm);
    float dy  = 0.5f * (yp - ym);
    float dxx = xp - 2.0f * u0 + xm;
    float dyy = yp - 2.0f * u0 + ym;
    float dxy = 0.25f * (pp - pm - mp + mm);

    int s = (A0 + a) * NYX + (C0 + c);
    size_t pl = (size_t)bt * SP + s;
    float kap = g_kg[pl];
    float m1  = g_m1[pl];
    float m2  = g_m2[pl];
    float h11 = g_h11[pl];
    float hxy = g_hxy[pl];
    float h22 = g_h22[pl];

    float r = u0 + kap * kap * u0 + m1 * dx + m2 * dy
            - (h11 * dxx + 2.0f * hxy * dxy + h22 * dyy);
    og[pl] = r;
}

// ---------------------------------------------------------------------------
// qx + deterministic reduction (two stages, fixed order).
// ---------------------------------------------------------------------------
__global__ void qx_reduce_k() {
    __shared__ float sm[256];
    int b = blockIdx.y;
    size_t base = (size_t)blockIdx.x * 4096;
    const float* xb = g_xg + (size_t)b * NT * SP;
    const float* wb = g_w  + (size_t)b * NT * SP;
    const float* vb = g_v  + (size_t)b * NT * SP;
    float sum = 0.0f;
    for (int i = threadIdx.x; i < 4096; i += 256) {
        size_t e = base + i;
        int t = (int)(e >> 16);
        int s = (int)(e & (SP - 1));
        float q;
        if (t == 0)       q = vb[s] - wb[SP + s];
        else if (t == 8)  q = -wb[7 * SP + s] + vb[8 * (size_t)SP + s];
        else              q = -wb[(size_t)(t - 1) * SP + s] + vb[e] + xb[e]
                              - wb[(size_t)(t + 1) * SP + s];
        sum += xb[e] * q;
    }
    sm[threadIdx.x] = sum;
    __syncthreads();
    for (int st = 128; st > 0; st >>= 1) {
        if (threadIdx.x < st) sm[threadIdx.x] += sm[threadIdx.x + st];
        __syncthreads();
    }
    if (threadIdx.x == 0) g_part[b * 160 + blockIdx.x] = sm[0];
}

__global__ void final_reduce_k(float* __restrict__ out) {
    int b = threadIdx.x;
    if (b < NB) {
        float s = 0.0f;
        for (int i = 0; i < 144; i++) s += g_part[b * 160 + i];
        out[OFF_XOUT + b] = s;
    }
}

// ---------------------------------------------------------------------------
extern "C" void kernel_launch(void* const* d_in, const int* in_sizes, int n_in,
                              void* d_out, int out_size) {
    const float* x  = (const float*)d_in[0];
    const float* w1 = (const float*)d_in[4];
    const float* w2 = (const float*)d_in[5];
    const float* w3 = (const float*)d_in[6];
    float* out = (float*)d_out;

    float *p1, *p2, *p3, *xg, *wg, *vg;
    cudaGetSymbolAddress((void**)&p1, g_p1);
    cudaGetSymbolAddress((void**)&p2, g_p2);
    cudaGetSymbolAddress((void**)&p3, g_p3);
    cudaGetSymbolAddress((void**)&xg, g_xg);
    cudaGetSymbolAddress((void**)&wg, g_w);
    cudaGetSymbolAddress((void**)&vg, g_v);

    const int RS = 264;
    const int smem1 = (9  * 6 * RS + 10 * 9  * 9) * 4;
    const int smem2 = (10 * 6 * RS + 10 * 10 * 9) * 4;
    const int smem3 = (20 * 6 * RS + 14 * 20 * 9) * 4;
    cudaFuncSetAttribute(conv3x3_k<9,  true >, cudaFuncAttributeMaxDynamicSharedMemorySize, smem1);
    cudaFuncSetAttribute(conv3x3_k<10, true >, cudaFuncAttributeMaxDynamicSharedMemorySize, smem2);
    cudaFuncSetAttribute(conv3x3_k<20, false>, cudaFuncAttributeMaxDynamicSharedMemorySize, smem3);

    conv3x3_k<9,  true ><<<dim3(1, 64, NB), dim3(32, 10), smem1>>>(x,  w1, p1, C1);
    conv3x3_k<10, true ><<<dim3(2, 64, NB), dim3(32, 10), smem2>>>(p1, w2, p2, C2);
    conv3x3_k<20, false><<<dim3(4, 64, NB), dim3(32, 14), smem3>>>(p2, w3, p3, C3);

    epiA_k<<<(NB * 27 * SP / 4 + 255) / 256, 256>>>(out);
    epiH_k<<<(NB * SP) / 256, 256>>>(out);
    scramble_k<<<(NB * NT * SP) / 256, 256>>>();

    transpose_k<<<dim3(8, 8, NB * NT), dim3(32, 8)>>>(x);
    applyM_k<<<dim3(8, 32, NB * NT), dim3(32, 8)>>>(xg, wg);
    applyM_k<<<dim3(8, 32, NB * NT), dim3(32, 8)>>>(wg, vg);
    qx_reduce_k<<<dim3(144, NB), 256>>>();
    final_reduce_k<<<1, 32>>>(out);
}

// round 3
// speedup vs baseline: 1.2173x; 1.2082x over previous
#include <cuda_runtime.h>
#include <cuda_bf16.h>
#include <cstdint>

#define NB 16
#define NT 9
#define NYX 256
#define SP 65536
#define C1 10
#define C2 20
#define C3 54

#define OFF_XOUT 0
#define OFF_KAP  16
#define OFF_M    9437200
#define OFF_H    28311568

typedef unsigned long long u64;

__device__ float g_p1[NB * C1 * SP];
__device__ float g_p2[NB * C2 * SP];
__device__ float g_p3[NB * C3 * SP];
__device__ float g_xg[NB * NT * SP];
__device__ float g_w [NB * NT * SP];
__device__ float g_v [NB * NT * SP];
__device__ float g_kg [NB * NT * SP];
__device__ float g_m1 [NB * NT * SP];
__device__ float g_m2 [NB * NT * SP];
__device__ float g_h11[NB * NT * SP];
__device__ float g_hxy[NB * NT * SP];
__device__ float g_h22[NB * NT * SP];
__device__ float g_part[NB * 160];

__device__ __forceinline__ float sp10(float x) {
    float z = 10.0f * x;
    return (fmaxf(z, 0.0f) + log1pf(expf(-fabsf(z)))) * 0.1f;
}

__device__ __forceinline__ u64 pk2(float lo, float hi) {
    u64 r; asm("mov.b64 %0, {%1, %2};" : "=l"(r) : "f"(lo), "f"(hi)); return r;
}
__device__ __forceinline__ float2 upk(u64 v) {
    float2 r; asm("mov.b64 {%0, %1}, %2;" : "=f"(r.x), "=f"(r.y) : "l"(v)); return r;
}
__device__ __forceinline__ void fma2(u64& d, u64 a, u64 b) {
    asm("fma.rn.f32x2 %0, %1, %2, %0;" : "+l"(d) : "l"(a), "l"(b));
}

// ---------------------------------------------------------------------------
// 3x3 SAME conv, packed f32x2 FMA. block (32, CO_CHUNK), 4 rows x 8 cols/thread.
// ---------------------------------------------------------------------------
template <int CIN, bool RELU_IN, int MAXT>
__global__ void __launch_bounds__(MAXT, 1)
conv3x3_k(const float* __restrict__ in,
          const float* __restrict__ wts,
          float* __restrict__ out, int COUT) {
    extern __shared__ float sh[];
    const int RS = 264;
    float* in_sh = sh;
    float* w_sh  = sh + CIN * 6 * RS;

    const int b = blockIdx.z;
    const int y0 = blockIdx.y * 4;
    const int chunk = blockIdx.x;
    const int nth = blockDim.x * blockDim.y;
    const int tid = threadIdx.y * 32 + threadIdx.x;

    const float* inb = in + (size_t)b * CIN * SP;
    for (int idx = tid; idx < CIN * 6 * 258; idx += nth) {
        int col = idx % 258;
        int tmp = idx / 258;
        int row = tmp % 6;
        int cin = tmp / 6;
        int gy = y0 - 1 + row;
        int gx = col - 1;
        float v = 0.0f;
        if (gy >= 0 && gy < NYX && gx >= 0 && gx < NYX) {
            v = inb[cin * SP + gy * NYX + gx];
            if (RELU_IN) v = fmaxf(v, 0.0f);
        }
        in_sh[(cin * 6 + row) * RS + col] = v;
    }
    const int wcnt = blockDim.y * CIN * 9;
    for (int idx = tid; idx < wcnt; idx += nth) {
        int co = idx / (CIN * 9);
        int g = chunk * blockDim.y + co;
        w_sh[idx] = (g < COUT) ? wts[(size_t)g * CIN * 9 + idx % (CIN * 9)] : 0.0f;
    }
    __syncthreads();

    const int co = chunk * blockDim.y + threadIdx.y;
    u64 acc[4][4];
#pragma unroll
    for (int r = 0; r < 4; r++)
#pragma unroll
        for (int q = 0; q < 4; q++) acc[r][q] = 0ull;

    const float* wrow = w_sh + threadIdx.y * CIN * 9;
    const int xbase = threadIdx.x * 8;

    for (int cin = 0; cin < CIN; ++cin) {
        u64 W[3][3];
#pragma unroll
        for (int ky = 0; ky < 3; ++ky)
#pragma unroll
            for (int j = 0; j < 3; ++j) {
                float w = wrow[cin * 9 + ky * 3 + j];
                W[ky][j] = pk2(w, w);
            }
        const float* base = &in_sh[cin * 6 * RS + xbase];
#pragma unroll
        for (int sr = 0; sr < 6; ++sr) {
            const float* rp = base + sr * RS;
            float t[10];
#pragma unroll
            for (int q = 0; q < 10; q++) t[q] = rp[q];
            u64 P0 = pk2(t[0], t[1]), P1 = pk2(t[2], t[3]),
                P2 = pk2(t[4], t[5]), P3 = pk2(t[6], t[7]), P4 = pk2(t[8], t[9]);
            u64 S1 = pk2(t[1], t[2]), S3 = pk2(t[3], t[4]),
                S5 = pk2(t[5], t[6]), S7 = pk2(t[7], t[8]);
#pragma unroll
            for (int ky = 0; ky < 3; ++ky) {
                int r = sr - ky;
                if (r >= 0 && r < 4) {
                    fma2(acc[r][0], P0, W[ky][0]); fma2(acc[r][0], S1, W[ky][1]); fma2(acc[r][0], P1, W[ky][2]);
                    fma2(acc[r][1], P1, W[ky][0]); fma2(acc[r][1], S3, W[ky][1]); fma2(acc[r][1], P2, W[ky][2]);
                    fma2(acc[r][2], P2, W[ky][0]); fma2(acc[r][2], S5, W[ky][1]); fma2(acc[r][2], P3, W[ky][2]);
                    fma2(acc[r][3], P3, W[ky][0]); fma2(acc[r][3], S7, W[ky][1]); fma2(acc[r][3], P4, W[ky][2]);
                }
            }
        }
    }

    if (co < COUT) {
        float* ob = out + ((size_t)b * COUT + co) * SP + (size_t)y0 * NYX + xbase;
#pragma unroll
        for (int r = 0; r < 4; ++r) {
            float2 o0 = upk(acc[r][0]), o1 = upk(acc[r][1]),
                   o2 = upk(acc[r][2]), o3 = upk(acc[r][3]);
            float4 v0 = make_float4(o0.x, o0.y, o1.x, o1.y);
            float4 v1 = make_float4(o2.x, o2.y, o3.x, o3.y);
            reinterpret_cast<float4*>(ob + (size_t)r * NYX)[0] = v0;
            reinterpret_cast<float4*>(ob + (size_t)r * NYX)[1] = v1;
        }
    }
}

// ---------------------------------------------------------------------------
// Fused: kappa_r + m_r outputs AND kg/m1/m2 plane grids, via smem staging.
// The scramble (t,y,x) <- flat L=9s+t is a reshape since channels are
// contiguous. grid (256, NB), block 256. Each block: L-chunk of 2304.
// ---------------------------------------------------------------------------
__global__ void epiA_scramble_k(float* __restrict__ out) {
    __shared__ float shk[2304], shm1[2304], shm2[2304];
    int b = blockIdx.y;
    int chunk = blockIdx.x;               // 0..255
    int L0 = chunk * 2304;
    int s0 = chunk * 256;
    const float* src = g_p3 + (size_t)b * C3 * SP;
    float* okap = out + OFF_KAP + (size_t)b * 9 * SP;
    float* om   = out + OFF_M   + (size_t)b * 18 * SP;
#pragma unroll
    for (int it = 0; it < 9; ++it) {
        int i = it * 256 + threadIdx.x;
        int L = L0 + i;
        float k  = sp10(src[L]);
        float m1 = src[9 * SP + L];
        float m2 = src[18 * SP + L];
        shk[i] = k; shm1[i] = m1; shm2[i] = m2;
        okap[L] = k;
        om[L] = m1;
        om[9 * SP + L] = m2;
    }
    __syncthreads();
#pragma unroll
    for (int it = 0; it < 9; ++it) {
        int i = it * 256 + threadIdx.x;
        int so = i & 255;
        int t = i >> 8;
        int si = 9 * so + t;
        size_t dst = ((size_t)b * 9 + t) * SP + s0 + so;
        g_kg[dst] = shk[si];
        g_m1[dst] = shm1[si];
        g_m2[dst] = shm2[si];
    }
}

// ---------------------------------------------------------------------------
// H_r transpose-write + h11/hxy/h22 plane grids.
// ---------------------------------------------------------------------------
__global__ void epiH_k(float* __restrict__ out) {
    int gid = blockIdx.x * blockDim.x + threadIdx.x;
    int b = gid >> 16;
    int s = gid & (SP - 1);
    const float* pb = g_p3 + (size_t)b * C3 * SP + s;
    float gm[NT], vx[NT], vy[NT];
#pragma unroll
    for (int t = 0; t < NT; t++) {
        gm[t] = sp10(pb[(size_t)(27 + t) * SP]);
        vx[t] = pb[(size_t)(36 + t) * SP];
        vy[t] = pb[(size_t)(45 + t) * SP];
    }
    const size_t PLANE = (size_t)SP * NT;
    size_t base = OFF_H + (size_t)b * 4 * PLANE + (size_t)s * NT;
    size_t pb2 = (size_t)b * NT * SP + s;
#pragma unroll
    for (int t = 0; t < NT; t++) {
        float h11 = gm[t] + vx[t] * vx[t];
        out[base + t] = h11;
        g_h11[pb2 + (size_t)t * SP] = h11;
    }
#pragma unroll
    for (int t = 0; t < NT; t++) {
        float xy = vx[t] * vy[t];
        out[base + PLANE + t]     = xy;
        out[base + 2 * PLANE + t] = xy;
        g_hxy[pb2 + (size_t)t * SP] = xy;
    }
#pragma unroll
    for (int t = 0; t < NT; t++) {
        float h22 = gm[t] + vy[t] * vy[t];
        out[base + 3 * PLANE + t] = h22;
        g_h22[pb2 + (size_t)t * SP] = h22;
    }
}

// ---------------------------------------------------------------------------
__global__ void transpose_k(const float* __restrict__ x) {
    __shared__ float tile[32][33];
    int b = blockIdx.z / NT, t = blockIdx.z % NT;
    const float* xb = x + ((size_t)b * NT + t) * SP;
    float* og = g_xg + ((size_t)b * NT + t) * SP;
    int Y0 = blockIdx.y * 32, X0 = blockIdx.x * 32;
#pragma unroll
    for (int k = 0; k < 4; k++) {
        int row = threadIdx.y + k * 8;
        tile[row][threadIdx.x] = xb[(size_t)(Y0 + row) * NYX + X0 + threadIdx.x];
    }
    __syncthreads();
#pragma unroll
    for (int k = 0; k < 4; k++) {
        int row = threadIdx.y + k * 8;
        og[(size_t)(X0 + row) * NYX + Y0 + threadIdx.x] = tile[threadIdx.x][row];
    }
}

// ---------------------------------------------------------------------------
__global__ void applyM_k(const float* __restrict__ u, float* __restrict__ og) {
    __shared__ float tile[10][36];
    int bt = blockIdx.z;
    int A0 = blockIdx.y * 8, C0 = blockIdx.x * 32;
    const float* ub = u + (size_t)bt * SP;
    int tid = threadIdx.y * 32 + threadIdx.x;
    for (int i = tid; i < 10 * 34; i += 256) {
        int rr = i / 34, cc = i % 34;
        int A = A0 - 1 + rr, C = C0 - 1 + cc;
        tile[rr][cc] = (A >= 0 && A < NYX && C >= 0 && C < NYX)
                       ? ub[(size_t)A * NYX + C] : 0.0f;
    }
    __syncthreads();
    int a = threadIdx.y, c = threadIdx.x;
    float u0 = tile[a + 1][c + 1];
    float xp = tile[a + 2][c + 1], xm = tile[a][c + 1];
    float yp = tile[a + 1][c + 2], ym = tile[a + 1][c];
    float pp = tile[a + 2][c + 2], pm = tile[a + 2][c];
    float mp = tile[a][c + 2],     mm = tile[a][c];
    float dx  = 0.5f * (xp - xm);
    float dy  = 0.5f * (yp - ym);
    float dxx = xp - 2.0f * u0 + xm;
    float dyy = yp - 2.0f * u0 + ym;
    float dxy = 0.25f * (pp - pm - mp + mm);

    int s = (A0 + a) * NYX + (C0 + c);
    size_t pl = (size_t)bt * SP + s;
    float kap = g_kg[pl];
    float m1  = g_m1[pl];
    float m2  = g_m2[pl];
    float h11 = g_h11[pl];
    float hxy = g_hxy[pl];
    float h22 = g_h22[pl];

    float r = u0 + kap * kap * u0 + m1 * dx + m2 * dy
            - (h11 * dxx + 2.0f * hxy * dxy + h22 * dyy);
    og[pl] = r;
}

// ---------------------------------------------------------------------------
__global__ void qx_reduce_k() {
    __shared__ float sm[256];
    int b = blockIdx.y;
    size_t base = (size_t)blockIdx.x * 4096;
    const float* xb = g_xg + (size_t)b * NT * SP;
    const float* wb = g_w  + (size_t)b * NT * SP;
    const float* vb = g_v  + (size_t)b * NT * SP;
    float sum = 0.0f;
    for (int i = threadIdx.x; i < 4096; i += 256) {
        size_t e = base + i;
        int t = (int)(e >> 16);
        int s = (int)(e & (SP - 1));
        float q;
        if (t == 0)       q = vb[s] - wb[SP + s];
        else if (t == 8)  q = -wb[7 * SP + s] + vb[8 * (size_t)SP + s];
        else              q = -wb[(size_t)(t - 1) * SP + s] + vb[e] + xb[e]
                              - wb[(size_t)(t + 1) * SP + s];
        sum += xb[e] * q;
    }
    sm[threadIdx.x] = sum;
    __syncthreads();
    for (int st = 128; st > 0; st >>= 1) {
        if (threadIdx.x < st) sm[threadIdx.x] += sm[threadIdx.x + st];
        __syncthreads();
    }
    if (threadIdx.x == 0) g_part[b * 160 + blockIdx.x] = sm[0];
}

__global__ void final_reduce_k(float* __restrict__ out) {
    int b = threadIdx.x;
    if (b < NB) {
        float s = 0.0f;
        for (int i = 0; i < 144; i++) s += g_part[b * 160 + i];
        out[OFF_XOUT + b] = s;
    }
}

// ---------------------------------------------------------------------------
extern "C" void kernel_launch(void* const* d_in, const int* in_sizes, int n_in,
                              void* d_out, int out_size) {
    const float* x  = (const float*)d_in[0];
    const float* w1 = (const float*)d_in[4];
    const float* w2 = (const float*)d_in[5];
    const float* w3 = (const float*)d_in[6];
    float* out = (float*)d_out;

    float *p1, *p2, *p3, *xg, *wg, *vg;
    cudaGetSymbolAddress((void**)&p1, g_p1);
    cudaGetSymbolAddress((void**)&p2, g_p2);
    cudaGetSymbolAddress((void**)&p3, g_p3);
    cudaGetSymbolAddress((void**)&xg, g_xg);
    cudaGetSymbolAddress((void**)&wg, g_w);
    cudaGetSymbolAddress((void**)&vg, g_v);

    const int RS = 264;
    const int smem1 = (9  * 6 * RS + 10 * 9  * 9) * 4;   // 60264
    const int smem2 = (10 * 6 * RS + 20 * 10 * 9) * 4;   // 70560
    const int smem3 = (20 * 6 * RS + 27 * 20 * 9) * 4;   // 146160
    cudaFuncSetAttribute((const void*)conv3x3_k<9,  true,  320>, cudaFuncAttributeMaxDynamicSharedMemorySize, smem1);
    cudaFuncSetAttribute((const void*)conv3x3_k<10, true,  640>, cudaFuncAttributeMaxDynamicSharedMemorySize, smem2);
    cudaFuncSetAttribute((const void*)conv3x3_k<20, false, 864>, cudaFuncAttributeMaxDynamicSharedMemorySize, smem3);

    // 1: transpose (independent of convs)
    transpose_k<<<dim3(8, 8, NB * NT), dim3(32, 8)>>>(x);
    // 2,3,4: conv chain — conv3 sits in the ncu-profiled launch slot
    conv3x3_k<9,  true,  320><<<dim3(1, 64, NB), dim3(32, 10), smem1>>>(x,  w1, p1, C1);
    conv3x3_k<10, true,  640><<<dim3(1, 64, NB), dim3(32, 20), smem2>>>(p1, w2, p2, C2);
    conv3x3_k<20, false, 864><<<dim3(2, 64, NB), dim3(32, 27), smem3>>>(p2, w3, p3, C3);

    // epilogues
    epiH_k<<<(NB * SP) / 256, 256>>>(out);
    epiA_scramble_k<<<dim3(256, NB), 256>>>(out);

    // PDE pipeline
    applyM_k<<<dim3(8, 32, NB * NT), dim3(32, 8)>>>(xg, wg);
    applyM_k<<<dim3(8, 32, NB * NT), dim3(32, 8)>>>(wg, vg);
    qx_reduce_k<<<dim3(144, NB), 256>>>();
    final_reduce_k<<<1, 32>>>(out);
}

// round 5
// speedup vs baseline: 1.2634x; 1.0379x over previous
#include <cuda_runtime.h>
#include <cuda_bf16.h>
#include <cstdint>

#define NB 16
#define NT 9
#define NYX 256
#define SP 65536
#define C1 10
#define C2 20
#define C3 54

#define OFF_XOUT 0
#define OFF_KAP  16
#define OFF_M    9437200
#define OFF_H    28311568

typedef unsigned long long u64;

__device__ float g_p1[NB * C1 * SP];
__device__ float g_p2[NB * C2 * SP];
__device__ float g_p3[NB * C3 * SP];
__device__ float g_xg[NB * NT * SP];
__device__ float g_w [NB * NT * SP];
__device__ float g_v [NB * NT * SP];
__device__ float g_kg [NB * NT * SP];
__device__ float g_m1 [NB * NT * SP];
__device__ float g_m2 [NB * NT * SP];
__device__ float g_h11[NB * NT * SP];
__device__ float g_hxy[NB * NT * SP];
__device__ float g_h22[NB * NT * SP];
__device__ float g_part[NB * 160];

__device__ __forceinline__ float sp10(float x) {
    float z = 10.0f * x;
    return (fmaxf(z, 0.0f) + log1pf(expf(-fabsf(z)))) * 0.1f;
}

__device__ __forceinline__ u64 pk2(float lo, float hi) {
    u64 r; asm("mov.b64 %0, {%1, %2};" : "=l"(r) : "f"(lo), "f"(hi)); return r;
}
__device__ __forceinline__ float2 upk(u64 v) {
    float2 r; asm("mov.b64 {%0, %1}, %2;" : "=f"(r.x), "=f"(r.y) : "l"(v)); return r;
}
__device__ __forceinline__ void fma2(u64& d, u64 a, u64 b) {
    asm("fma.rn.f32x2 %0, %1, %2, %0;" : "+l"(d) : "l"(a), "l"(b));
}

// ---------------------------------------------------------------------------
// 3x3 SAME conv, f32x2 FMA, 4 couts x 2 rows x 8 cols per thread.
// block (32, YG); cout = (chunk*YG + threadIdx.y)*4 + j.
// grid (ceil(COUT/(YG*4)), 128, NB).
// smem: input tile CIN x 4rows x 264 + this chunk's weights YG*4 x CIN x 9.
// ---------------------------------------------------------------------------
template <int CIN, bool RELU_IN, int YG, int COUT>
__global__ void __launch_bounds__(32 * YG, 2)
conv3x3_k(const float* __restrict__ in,
          const float* __restrict__ wts,
          float* __restrict__ out) {
    extern __shared__ float sh[];
    const int RS = 264;
    float* in_sh = sh;                       // CIN*4*RS
    float* w_sh  = sh + CIN * 4 * RS;        // YG*4*CIN*9

    const int b = blockIdx.z;
    const int y0 = blockIdx.y * 2;
    const int chunk = blockIdx.x;
    const int co_base = chunk * YG * 4;
    const int nth = 32 * YG;
    const int tid = threadIdx.y * 32 + threadIdx.x;

    const float* inb = in + (size_t)b * CIN * SP;
    for (int idx = tid; idx < CIN * 4 * 258; idx += nth) {
        int col = idx % 258;
        int tmp = idx / 258;
        int row = tmp % 4;
        int cin = tmp / 4;
        int gy = y0 - 1 + row;
        int gx = col - 1;
        float v = 0.0f;
        if (gy >= 0 && gy < NYX && gx >= 0 && gx < NYX) {
            v = inb[cin * SP + gy * NYX + gx];
            if (RELU_IN) v = fmaxf(v, 0.0f);
        }
        in_sh[(cin * 4 + row) * RS + col] = v;
    }
    for (int idx = tid; idx < YG * 4 * CIN * 9; idx += nth) {
        int g = co_base + idx / (CIN * 9);
        w_sh[idx] = (g < COUT) ? wts[(size_t)g * CIN * 9 + idx % (CIN * 9)] : 0.0f;
    }
    __syncthreads();

    u64 acc[2][4][4];                        // [row][cout j][pair]
#pragma unroll
    for (int r = 0; r < 2; r++)
#pragma unroll
        for (int j = 0; j < 4; j++)
#pragma unroll
            for (int q = 0; q < 4; q++) acc[r][j][q] = 0ull;

    const int xbase = threadIdx.x * 8;
    const float* wb = w_sh + threadIdx.y * 4 * CIN * 9;

    for (int cin = 0; cin < CIN; ++cin) {
        const float* base = &in_sh[cin * 4 * RS + xbase];
#pragma unroll
        for (int sr = 0; sr < 4; ++sr) {
            const float* rp = base + sr * RS;
            float t[10];
#pragma unroll
            for (int q = 0; q < 10; q++) t[q] = rp[q];
            u64 P0 = pk2(t[0], t[1]), P1 = pk2(t[2], t[3]),
                P2 = pk2(t[4], t[5]), P3 = pk2(t[6], t[7]), P4 = pk2(t[8], t[9]);
            u64 S1 = pk2(t[1], t[2]), S3 = pk2(t[3], t[4]),
                S5 = pk2(t[5], t[6]), S7 = pk2(t[7], t[8]);
#pragma unroll
            for (int ky = 0; ky < 3; ++ky) {
                int r = sr - ky;
                if (r >= 0 && r < 2) {
#pragma unroll
                    for (int j = 0; j < 4; ++j) {
                        const float* wr = wb + (j * CIN + cin) * 9 + ky * 3;
                        float w0 = wr[0], w1 = wr[1], w2 = wr[2];
                        u64 W0 = pk2(w0, w0), W1 = pk2(w1, w1), W2 = pk2(w2, w2);
                        fma2(acc[r][j][0], P0, W0); fma2(acc[r][j][0], S1, W1); fma2(acc[r][j][0], P1, W2);
                        fma2(acc[r][j][1], P1, W0); fma2(acc[r][j][1], S3, W1); fma2(acc[r][j][1], P2, W2);
                        fma2(acc[r][j][2], P2, W0); fma2(acc[r][j][2], S5, W1); fma2(acc[r][j][2], P3, W2);
                        fma2(acc[r][j][3], P3, W0); fma2(acc[r][j][3], S7, W1); fma2(acc[r][j][3], P4, W2);
                    }
                }
            }
        }
    }

#pragma unroll
    for (int r = 0; r < 2; ++r) {
        int gy = y0 + r;
#pragma unroll
        for (int j = 0; j < 4; ++j) {
            int co = co_base + threadIdx.y * 4 + j;
            if (co < COUT) {
                float* ob = out + ((size_t)b * COUT + co) * SP + (size_t)gy * NYX + xbase;
                float2 o0 = upk(acc[r][j][0]), o1 = upk(acc[r][j][1]),
                       o2 = upk(acc[r][j][2]), o3 = upk(acc[r][j][3]);
                reinterpret_cast<float4*>(ob)[0] = make_float4(o0.x, o0.y, o1.x, o1.y);
                reinterpret_cast<float4*>(ob)[1] = make_float4(o2.x, o2.y, o3.x, o3.y);
            }
        }
    }
}

// ---------------------------------------------------------------------------
// Fused: kappa_r + m_r outputs AND kg/m1/m2 plane grids, via smem staging.
// ---------------------------------------------------------------------------
__global__ void epiA_scramble_k(float* __restrict__ out) {
    __shared__ float shk[2304], shm1[2304], shm2[2304];
    int b = blockIdx.y;
    int chunk = blockIdx.x;
    int L0 = chunk * 2304;
    int s0 = chunk * 256;
    const float* src = g_p3 + (size_t)b * C3 * SP;
    float* okap = out + OFF_KAP + (size_t)b * 9 * SP;
    float* om   = out + OFF_M   + (size_t)b * 18 * SP;
#pragma unroll
    for (int it = 0; it < 9; ++it) {
        int i = it * 256 + threadIdx.x;
        int L = L0 + i;
        float k  = sp10(src[L]);
        float m1 = src[9 * SP + L];
        float m2 = src[18 * SP + L];
        shk[i] = k; shm1[i] = m1; shm2[i] = m2;
        okap[L] = k;
        om[L] = m1;
        om[9 * SP + L] = m2;
    }
    __syncthreads();
#pragma unroll
    for (int it = 0; it < 9; ++it) {
        int i = it * 256 + threadIdx.x;
        int so = i & 255;
        int t = i >> 8;
        int si = 9 * so + t;
        size_t dst = ((size_t)b * 9 + t) * SP + s0 + so;
        g_kg[dst] = shk[si];
        g_m1[dst] = shm1[si];
        g_m2[dst] = shm2[si];
    }
}

// ---------------------------------------------------------------------------
__global__ void epiH_k(float* __restrict__ out) {
    int gid = blockIdx.x * blockDim.x + threadIdx.x;
    int b = gid >> 16;
    int s = gid & (SP - 1);
    const float* pb = g_p3 + (size_t)b * C3 * SP + s;
    float gm[NT], vx[NT], vy[NT];
#pragma unroll
    for (int t = 0; t < NT; t++) {
        gm[t] = sp10(pb[(size_t)(27 + t) * SP]);
        vx[t] = pb[(size_t)(36 + t) * SP];
        vy[t] = pb[(size_t)(45 + t) * SP];
    }
    const size_t PLANE = (size_t)SP * NT;
    size_t base = OFF_H + (size_t)b * 4 * PLANE + (size_t)s * NT;
    size_t pb2 = (size_t)b * NT * SP + s;
#pragma unroll
    for (int t = 0; t < NT; t++) {
        float h11 = gm[t] + vx[t] * vx[t];
        out[base + t] = h11;
        g_h11[pb2 + (size_t)t * SP] = h11;
    }
#pragma unroll
    for (int t = 0; t < NT; t++) {
        float xy = vx[t] * vy[t];
        out[base + PLANE + t]     = xy;
        out[base + 2 * PLANE + t] = xy;
        g_hxy[pb2 + (size_t)t * SP] = xy;
    }
#pragma unroll
    for (int t = 0; t < NT; t++) {
        float h22 = gm[t] + vy[t] * vy[t];
        out[base + 3 * PLANE + t] = h22;
        g_h22[pb2 + (size_t)t * SP] = h22;
    }
}

// ---------------------------------------------------------------------------
__global__ void transpose_k(const float* __restrict__ x) {
    __shared__ float tile[32][33];
    int b = blockIdx.z / NT, t = blockIdx.z % NT;
    const float* xb = x + ((size_t)b * NT + t) * SP;
    float* og = g_xg + ((size_t)b * NT + t) * SP;
    int Y0 = blockIdx.y * 32, X0 = blockIdx.x * 32;
#pragma unroll
    for (int k = 0; k < 4; k++) {
        int row = threadIdx.y + k * 8;
        tile[row][threadIdx.x] = xb[(size_t)(Y0 + row) * NYX + X0 + threadIdx.x];
    }
    __syncthreads();
#pragma unroll
    for (int k = 0; k < 4; k++) {
        int row = threadIdx.y + k * 8;
        og[(size_t)(X0 + row) * NYX + Y0 + threadIdx.x] = tile[threadIdx.x][row];
    }
}

// ---------------------------------------------------------------------------
__global__ void applyM_k(const float* __restrict__ u, float* __restrict__ og) {
    __shared__ float tile[10][36];
    int bt = blockIdx.z;
    int A0 = blockIdx.y * 8, C0 = blockIdx.x * 32;
    const float* ub = u + (size_t)bt * SP;
    int tid = threadIdx.y * 32 + threadIdx.x;
    for (int i = tid; i < 10 * 34; i += 256) {
        int rr = i / 34, cc = i % 34;
        int A = A0 - 1 + rr, C = C0 - 1 + cc;
        tile[rr][cc] = (A >= 0 && A < NYX && C >= 0 && C < NYX)
                       ? ub[(size_t)A * NYX + C] : 0.0f;
    }
    __syncthreads();
    int a = threadIdx.y, c = threadIdx.x;
    float u0 = tile[a + 1][c + 1];
    float xp = tile[a + 2][c + 1], xm = tile[a][c + 1];
    float yp = tile[a + 1][c + 2], ym = tile[a + 1][c];
    float pp = tile[a + 2][c + 2], pm = tile[a + 2][c];
    float mp = tile[a][c + 2],     mm = tile[a][c];
    float dx  = 0.5f * (xp - xm);
    float dy  = 0.5f * (yp - ym);
    float dxx = xp - 2.0f * u0 + xm;
    float dyy = yp - 2.0f * u0 + ym;
    float dxy = 0.25f * (pp - pm - mp + mm);

    int s = (A0 + a) * NYX + (C0 + c);
    size_t pl = (size_t)bt * SP + s;
    float kap = g_kg[pl];
    float m1  = g_m1[pl];
    float m2  = g_m2[pl];
    float h11 = g_h11[pl];
    float hxy = g_hxy[pl];
    float h22 = g_h22[pl];

    float r = u0 + kap * kap * u0 + m1 * dx + m2 * dy
            - (h11 * dxx + 2.0f * hxy * dxy + h22 * dyy);
    og[pl] = r;
}

// ---------------------------------------------------------------------------
__global__ void qx_reduce_k() {
    __shared__ float sm[256];
    int b = blockIdx.y;
    size_t base = (size_t)blockIdx.x * 4096;
    const float* xb = g_xg + (size_t)b * NT * SP;
    const float* wb = g_w  + (size_t)b * NT * SP;
    const float* vb = g_v  + (size_t)b * NT * SP;
    float sum = 0.0f;
    for (int i = threadIdx.x; i < 4096; i += 256) {
        size_t e = base + i;
        int t = (int)(e >> 16);
        int s = (int)(e & (SP - 1));
        float q;
        if (t == 0)       q = vb[s] - wb[SP + s];
        else if (t == 8)  q = -wb[7 * SP + s] + vb[8 * (size_t)SP + s];
        else              q = -wb[(size_t)(t - 1) * SP + s] + vb[e] + xb[e]
                              - wb[(size_t)(t + 1) * SP + s];
        sum += xb[e] * q;
    }
    sm[threadIdx.x] = sum;
    __syncthreads();
    for (int st = 128; st > 0; st >>= 1) {
        if (threadIdx.x < st) sm[threadIdx.x] += sm[threadIdx.x + st];
        __syncthreads();
    }
    if (threadIdx.x == 0) g_part[b * 160 + blockIdx.x] = sm[0];
}

__global__ void final_reduce_k(float* __restrict__ out) {
    int b = threadIdx.x;
    if (b < NB) {
        float s = 0.0f;
        for (int i = 0; i < 144; i++) s += g_part[b * 160 + i];
        out[OFF_XOUT + b] = s;
    }
}

// ---------------------------------------------------------------------------
extern "C" void kernel_launch(void* const* d_in, const int* in_sizes, int n_in,
                              void* d_out, int out_size) {
    const float* x  = (const float*)d_in[0];
    const float* w1 = (const float*)d_in[4];
    const float* w2 = (const float*)d_in[5];
    const float* w3 = (const float*)d_in[6];
    float* out = (float*)d_out;

    float *p1, *p2, *p3, *xg, *wg, *vg;
    cudaGetSymbolAddress((void**)&p1, g_p1);
    cudaGetSymbolAddress((void**)&p2, g_p2);
    cudaGetSymbolAddress((void**)&p3, g_p3);
    cudaGetSymbolAddress((void**)&xg, g_xg);
    cudaGetSymbolAddress((void**)&wg, g_w);
    cudaGetSymbolAddress((void**)&vg, g_v);

    const int RS = 264;
    const int smem1 = (9  * 4 * RS + 12 * 9  * 9) * 4;   // 42,336
    const int smem2 = (10 * 4 * RS + 20 * 10 * 9) * 4;   // 49,440
    const int smem3 = (20 * 4 * RS + 28 * 20 * 9) * 4;   // 104,640
    cudaFuncSetAttribute((const void*)conv3x3_k<9,  true,  3, C1>, cudaFuncAttributeMaxDynamicSharedMemorySize, smem1);
    cudaFuncSetAttribute((const void*)conv3x3_k<10, true,  5, C2>, cudaFuncAttributeMaxDynamicSharedMemorySize, smem2);
    cudaFuncSetAttribute((const void*)conv3x3_k<20, false, 7, C3>, cudaFuncAttributeMaxDynamicSharedMemorySize, smem3);

    // 1: transpose (independent of convs)
    transpose_k<<<dim3(8, 8, NB * NT), dim3(32, 8)>>>(x);
    // 2,3,4: conv chain — conv3 in the profiled launch slot
    conv3x3_k<9,  true,  3, C1><<<dim3(1, 128, NB), dim3(32, 3), smem1>>>(x,  w1, p1);
    conv3x3_k<10, true,  5, C2><<<dim3(1, 128, NB), dim3(32, 5), smem2>>>(p1, w2, p2);
    conv3x3_k<20, false, 7, C3><<<dim3(2, 128, NB), dim3(32, 7), smem3>>>(p2, w3, p3);

    // epilogues
    epiH_k<<<(NB * SP) / 256, 256>>>(out);
    epiA_scramble_k<<<dim3(256, NB), 256>>>(out);

    // PDE pipeline
    applyM_k<<<dim3(8, 32, NB * NT), dim3(32, 8)>>>(xg, wg);
    applyM_k<<<dim3(8, 32, NB * NT), dim3(32, 8)>>>(wg, vg);
    qx_reduce_k<<<dim3(144, NB), 256>>>();
    final_reduce_k<<<1, 32>>>(out);
}

// round 6
// speedup vs baseline: 1.3048x; 1.0328x over previous
#include <cuda_runtime.h>
#include <cuda_bf16.h>
#include <cstdint>

#define NB 16
#define NT 9
#define NYX 256
#define SP 65536
#define C1 10
#define C2 20
#define C3 54

#define OFF_XOUT 0
#define OFF_KAP  16
#define OFF_M    9437200
#define OFF_H    28311568

typedef unsigned long long u64;

__device__ float g_p1[NB * C1 * SP];
__device__ float g_p2[NB * C2 * SP];
__device__ float g_p3[NB * C3 * SP];
__device__ float g_xg[NB * NT * SP];
__device__ float g_w [NB * NT * SP];
__device__ float g_v [NB * NT * SP];
__device__ float g_kg [NB * NT * SP];
__device__ float g_m1 [NB * NT * SP];
__device__ float g_m2 [NB * NT * SP];
__device__ float g_h11[NB * NT * SP];
__device__ float g_hxy[NB * NT * SP];
__device__ float g_h22[NB * NT * SP];
__device__ float g_part[NB * 160];

__device__ __forceinline__ float sp10(float x) {
    float z = 10.0f * x;
    return (fmaxf(z, 0.0f) + log1pf(expf(-fabsf(z)))) * 0.1f;
}

__device__ __forceinline__ u64 pk2(float lo, float hi) {
    u64 r; asm("mov.b64 %0, {%1, %2};" : "=l"(r) : "f"(lo), "f"(hi)); return r;
}
__device__ __forceinline__ float2 upk(u64 v) {
    float2 r; asm("mov.b64 {%0, %1}, %2;" : "=f"(r.x), "=f"(r.y) : "l"(v)); return r;
}
__device__ __forceinline__ void fma2(u64& d, u64 a, u64 b) {
    asm("fma.rn.f32x2 %0, %1, %2, %0;" : "+l"(d) : "l"(a), "l"(b));
}

// ---------------------------------------------------------------------------
// 3x3 SAME conv. f32x2 packs TWO OUTPUT CHANNELS per accumulator.
// Weights pre-paired in smem as u64 (w[2p], w[2p+1]) -> uniform LDS.64, 0 movs.
// Inputs duplicated (t,t) at runtime (1 mov each, 6 per src row).
// Thread: 1 output row, 4 px (cols 4*tid.x+px), 3 copairs = 6 couts.
// Block (32, YC): tid.y = copair-group. grid (2, 256, NB).
// Tile: quartered layout addr=(c&3)*34+(c>>2), stride 136/row -> the
// stride-4-column reads are lane-consecutive, conflict-free.
// ---------------------------------------------------------------------------
template <int CIN, bool RELU_IN, int YC, int COUT>
__global__ void __launch_bounds__(32 * YC, 3)
conv3x3_k(const float* __restrict__ in,
          const float* __restrict__ wts,
          float* __restrict__ out) {
    extern __shared__ float sh[];
    const int TS = 136;                      // words per tile row
    const int NP = YC * 3;                   // copairs total
    float* in_sh = sh;                       // CIN*3*TS floats
    u64*   w_sh  = (u64*)(sh + CIN * 3 * TS);// [CIN*9][NP] u64

    const int b  = blockIdx.z;
    const int y0 = blockIdx.y;               // output row
    const int x0 = blockIdx.x * 128;         // col base of this half-row
    const int nth = 32 * YC;
    const int tid = threadIdx.y * 32 + threadIdx.x;

    // ---- fill tile: 3 src rows (y0-1..y0+1), 130 cols (x0-1 .. x0+128) ----
    const float* inb = in + (size_t)b * CIN * SP;
    for (int idx = tid; idx < CIN * 3 * 130; idx += nth) {
        int c  = idx % 130;
        int rr = (idx / 130) % 3;
        int ci = idx / 390;
        int gy = y0 - 1 + rr;
        int gx = x0 - 1 + c;
        float v = 0.0f;
        if (gy >= 0 && gy < NYX && gx >= 0 && gx < NYX) {
            v = inb[ci * SP + gy * NYX + gx];
            if (RELU_IN) v = fmaxf(v, 0.0f);
        }
        in_sh[(ci * 3 + rr) * TS + (c & 3) * 34 + (c >> 2)] = v;
    }
    // ---- fill paired weights ----
    for (int idx = tid; idx < CIN * 9 * NP; idx += nth) {
        int p   = idx % NP;
        int tc  = idx / NP;
        int ci  = tc / 9;
        int tap = tc % 9;
        int c0 = 2 * p, c1 = 2 * p + 1;
        float lo = (c0 < COUT) ? wts[((size_t)c0 * CIN + ci) * 9 + tap] : 0.0f;
        float hi = (c1 < COUT) ? wts[((size_t)c1 * CIN + ci) * 9 + tap] : 0.0f;
        w_sh[idx] = pk2(lo, hi);
    }
    __syncthreads();

    const int pbase = threadIdx.y * 3;
    u64 acc[3][4];
#pragma unroll
    for (int pp = 0; pp < 3; pp++)
#pragma unroll
        for (int q = 0; q < 4; q++) acc[pp][q] = 0ull;

    for (int cin = 0; cin < CIN; ++cin) {
#pragma unroll
        for (int sr = 0; sr < 3; ++sr) {     // src row; ky == sr
            const float* rp = in_sh + (cin * 3 + sr) * TS + threadIdx.x;
            float t0 = rp[0],   t1 = rp[34], t2 = rp[68],
                  t3 = rp[102], t4 = rp[1],  t5 = rp[35];
            u64 D0 = pk2(t0, t0), D1 = pk2(t1, t1), D2 = pk2(t2, t2),
                D3 = pk2(t3, t3), D4 = pk2(t4, t4), D5 = pk2(t5, t5);
            const u64* wr = w_sh + (size_t)(cin * 9 + sr * 3) * NP + pbase;
#pragma unroll
            for (int pp = 0; pp < 3; ++pp) {
                u64 W0 = wr[pp], W1 = wr[NP + pp], W2 = wr[2 * NP + pp];
                fma2(acc[pp][0], D0, W0); fma2(acc[pp][0], D1, W1); fma2(acc[pp][0], D2, W2);
                fma2(acc[pp][1], D1, W0); fma2(acc[pp][1], D2, W1); fma2(acc[pp][1], D3, W2);
                fma2(acc[pp][2], D2, W0); fma2(acc[pp][2], D3, W1); fma2(acc[pp][2], D4, W2);
                fma2(acc[pp][3], D3, W0); fma2(acc[pp][3], D4, W1); fma2(acc[pp][3], D5, W2);
            }
        }
    }

    // ---- store: per copair, two float4 stores (co, co+1) ----
    const int xb = x0 + threadIdx.x * 4;
#pragma unroll
    for (int pp = 0; pp < 3; ++pp) {
        int p = pbase + pp;
        int c0 = 2 * p, c1 = 2 * p + 1;
        float2 a0 = upk(acc[pp][0]), a1 = upk(acc[pp][1]),
               a2 = upk(acc[pp][2]), a3 = upk(acc[pp][3]);
        if (c0 < COUT)
            *reinterpret_cast<float4*>(out + ((size_t)b * COUT + c0) * SP + (size_t)y0 * NYX + xb)
                = make_float4(a0.x, a1.x, a2.x, a3.x);
        if (c1 < COUT)
            *reinterpret_cast<float4*>(out + ((size_t)b * COUT + c1) * SP + (size_t)y0 * NYX + xb)
                = make_float4(a0.y, a1.y, a2.y, a3.y);
    }
}

// ---------------------------------------------------------------------------
// Fused: kappa_r + m_r outputs AND kg/m1/m2 plane grids, via smem staging.
// ---------------------------------------------------------------------------
__global__ void epiA_scramble_k(float* __restrict__ out) {
    __shared__ float shk[2304], shm1[2304], shm2[2304];
    int b = blockIdx.y;
    int chunk = blockIdx.x;
    int L0 = chunk * 2304;
    int s0 = chunk * 256;
    const float* src = g_p3 + (size_t)b * C3 * SP;
    float* okap = out + OFF_KAP + (size_t)b * 9 * SP;
    float* om   = out + OFF_M   + (size_t)b * 18 * SP;
#pragma unroll
    for (int it = 0; it < 9; ++it) {
        int i = it * 256 + threadIdx.x;
        int L = L0 + i;
        float k  = sp10(src[L]);
        float m1 = src[9 * SP + L];
        float m2 = src[18 * SP + L];
        shk[i] = k; shm1[i] = m1; shm2[i] = m2;
        okap[L] = k;
        om[L] = m1;
        om[9 * SP + L] = m2;
    }
    __syncthreads();
#pragma unroll
    for (int it = 0; it < 9; ++it) {
        int i = it * 256 + threadIdx.x;
        int so = i & 255;
        int t = i >> 8;
        int si = 9 * so + t;
        size_t dst = ((size_t)b * 9 + t) * SP + s0 + so;
        g_kg[dst] = shk[si];
        g_m1[dst] = shm1[si];
        g_m2[dst] = shm2[si];
    }
}

// ---------------------------------------------------------------------------
__global__ void epiH_k(float* __restrict__ out) {
    int gid = blockIdx.x * blockDim.x + threadIdx.x;
    int b = gid >> 16;
    int s = gid & (SP - 1);
    const float* pb = g_p3 + (size_t)b * C3 * SP + s;
    float gm[NT], vx[NT], vy[NT];
#pragma unroll
    for (int t = 0; t < NT; t++) {
        gm[t] = sp10(pb[(size_t)(27 + t) * SP]);
        vx[t] = pb[(size_t)(36 + t) * SP];
        vy[t] = pb[(size_t)(45 + t) * SP];
    }
    const size_t PLANE = (size_t)SP * NT;
    size_t base = OFF_H + (size_t)b * 4 * PLANE + (size_t)s * NT;
    size_t pb2 = (size_t)b * NT * SP + s;
#pragma unroll
    for (int t = 0; t < NT; t++) {
        float h11 = gm[t] + vx[t] * vx[t];
        out[base + t] = h11;
        g_h11[pb2 + (size_t)t * SP] = h11;
    }
#pragma unroll
    for (int t = 0; t < NT; t++) {
        float xy = vx[t] * vy[t];
        out[base + PLANE + t]     = xy;
        out[base + 2 * PLANE + t] = xy;
        g_hxy[pb2 + (size_t)t * SP] = xy;
    }
#pragma unroll
    for (int t = 0; t < NT; t++) {
        float h22 = gm[t] + vy[t] * vy[t];
        out[base + 3 * PLANE + t] = h22;
        g_h22[pb2 + (size_t)t * SP] = h22;
    }
}

// ---------------------------------------------------------------------------
__global__ void transpose_k(const float* __restrict__ x) {
    __shared__ float tile[32][33];
    int b = blockIdx.z / NT, t = blockIdx.z % NT;
    const float* xb = x + ((size_t)b * NT + t) * SP;
    float* og = g_xg + ((size_t)b * NT + t) * SP;
    int Y0 = blockIdx.y * 32, X0 = blockIdx.x * 32;
#pragma unroll
    for (int k = 0; k < 4; k++) {
        int row = threadIdx.y + k * 8;
        tile[row][threadIdx.x] = xb[(size_t)(Y0 + row) * NYX + X0 + threadIdx.x];
    }
    __syncthreads();
#pragma unroll
    for (int k = 0; k < 4; k++) {
        int row = threadIdx.y + k * 8;
        og[(size_t)(X0 + row) * NYX + Y0 + threadIdx.x] = tile[threadIdx.x][row];
    }
}

// ---------------------------------------------------------------------------
__global__ void applyM_k(const float* __restrict__ u, float* __restrict__ og) {
    __shared__ float tile[10][36];
    int bt = blockIdx.z;
    int A0 = blockIdx.y * 8, C0 = blockIdx.x * 32;
    const float* ub = u + (size_t)bt * SP;
    int tid = threadIdx.y * 32 + threadIdx.x;
    for (int i = tid; i < 10 * 34; i += 256) {
        int rr = i / 34, cc = i % 34;
        int A = A0 - 1 + rr, C = C0 - 1 + cc;
        tile[rr][cc] = (A >= 0 && A < NYX && C >= 0 && C < NYX)
                       ? ub[(size_t)A * NYX + C] : 0.0f;
    }
    __syncthreads();
    int a = threadIdx.y, c = threadIdx.x;
    float u0 = tile[a + 1][c + 1];
    float xp = tile[a + 2][c + 1], xm = tile[a][c + 1];
    float yp = tile[a + 1][c + 2], ym = tile[a + 1][c];
    float pp = tile[a + 2][c + 2], pm = tile[a + 2][c];
    float mp = tile[a][c + 2],     mm = tile[a][c];
    float dx  = 0.5f * (xp - xm);
    float dy  = 0.5f * (yp - ym);
    float dxx = xp - 2.0f * u0 + xm;
    float dyy = yp - 2.0f * u0 + ym;
    float dxy = 0.25f * (pp - pm - mp + mm);

    int s = (A0 + a) * NYX + (C0 + c);
    size_t pl = (size_t)bt * SP + s;
    float kap = g_kg[pl];
    float m1  = g_m1[pl];
    float m2  = g_m2[pl];
    float h11 = g_h11[pl];
    float hxy = g_hxy[pl];
    float h22 = g_h22[pl];

    float r = u0 + kap * kap * u0 + m1 * dx + m2 * dy
            - (h11 * dxx + 2.0f * hxy * dxy + h22 * dyy);
    og[pl] = r;
}

// ---------------------------------------------------------------------------
__global__ void qx_reduce_k() {
    __shared__ float sm[256];
    int b = blockIdx.y;
    size_t base = (size_t)blockIdx.x * 4096;
    const float* xb = g_xg + (size_t)b * NT * SP;
    const float* wb = g_w  + (size_t)b * NT * SP;
    const float* vb = g_v  + (size_t)b * NT * SP;
    float sum = 0.0f;
    for (int i = threadIdx.x; i < 4096; i += 256) {
        size_t e = base + i;
        int t = (int)(e >> 16);
        int s = (int)(e & (SP - 1));
        float q;
        if (t == 0)       q = vb[s] - wb[SP + s];
        else if (t == 8)  q = -wb[7 * SP + s] + vb[8 * (size_t)SP + s];
        else              q = -wb[(size_t)(t - 1) * SP + s] + vb[e] + xb[e]
                              - wb[(size_t)(t + 1) * SP + s];
        sum += xb[e] * q;
    }
    sm[threadIdx.x] = sum;
    __syncthreads();
    for (int st = 128; st > 0; st >>= 1) {
        if (threadIdx.x < st) sm[threadIdx.x] += sm[threadIdx.x + st];
        __syncthreads();
    }
    if (threadIdx.x == 0) g_part[b * 160 + blockIdx.x] = sm[0];
}

__global__ void final_reduce_k(float* __restrict__ out) {
    int b = threadIdx.x;
    if (b < NB) {
        float s = 0.0f;
        for (int i = 0; i < 144; i++) s += g_part[b * 160 + i];
        out[OFF_XOUT + b] = s;
    }
}

// ---------------------------------------------------------------------------
extern "C" void kernel_launch(void* const* d_in, const int* in_sizes, int n_in,
                              void* d_out, int out_size) {
    const float* x  = (const float*)d_in[0];
    const float* w1 = (const float*)d_in[4];
    const float* w2 = (const float*)d_in[5];
    const float* w3 = (const float*)d_in[6];
    float* out = (float*)d_out;

    float *p1, *p2, *p3, *xg, *wg, *vg;
    cudaGetSymbolAddress((void**)&p1, g_p1);
    cudaGetSymbolAddress((void**)&p2, g_p2);
    cudaGetSymbolAddress((void**)&p3, g_p3);
    cudaGetSymbolAddress((void**)&xg, g_xg);
    cudaGetSymbolAddress((void**)&wg, g_w);
    cudaGetSymbolAddress((void**)&vg, g_v);

    // smem sizes: tile CIN*3*136*4 + weights CIN*9*NP*8
    const int smem1 = 9  * 3 * 136 * 4 + 9  * 9 * 6  * 8;   // 18,576
    const int smem2 = 10 * 3 * 136 * 4 + 10 * 9 * 12 * 8;   // 24,960
    const int smem3 = 20 * 3 * 136 * 4 + 20 * 9 * 27 * 8;   // 71,520
    cudaFuncSetAttribute((const void*)conv3x3_k<9,  true,  2, C1>, cudaFuncAttributeMaxDynamicSharedMemorySize, smem1);
    cudaFuncSetAttribute((const void*)conv3x3_k<10, true,  4, C2>, cudaFuncAttributeMaxDynamicSharedMemorySize, smem2);
    cudaFuncSetAttribute((const void*)conv3x3_k<20, false, 9, C3>, cudaFuncAttributeMaxDynamicSharedMemorySize, smem3);

    // 1: transpose (independent of convs)
    transpose_k<<<dim3(8, 8, NB * NT), dim3(32, 8)>>>(x);
    // 2,3,4: conv chain — conv3 in the profiled launch slot
    conv3x3_k<9,  true,  2, C1><<<dim3(2, 256, NB), dim3(32, 2), smem1>>>(x,  w1, p1);
    conv3x3_k<10, true,  4, C2><<<dim3(2, 256, NB), dim3(32, 4), smem2>>>(p1, w2, p2);
    conv3x3_k<20, false, 9, C3><<<dim3(2, 256, NB), dim3(32, 9), smem3>>>(p2, w3, p3);

    // epilogues
    epiH_k<<<(NB * SP) / 256, 256>>>(out);
    epiA_scramble_k<<<dim3(256, NB), 256>>>(out);

    // PDE pipeline
    applyM_k<<<dim3(8, 32, NB * NT), dim3(32, 8)>>>(xg, wg);
    applyM_k<<<dim3(8, 32, NB * NT), dim3(32, 8)>>>(wg, vg);
    qx_reduce_k<<<dim3(144, NB), 256>>>();
    final_reduce_k<<<1, 32>>>(out);
}

// round 7
// speedup vs baseline: 1.3282x; 1.0179x over previous
#include <cuda_runtime.h>
#include <cuda_bf16.h>
#include <cstdint>

#define NB 16
#define NT 9
#define NYX 256
#define SP 65536
#define C1 10
#define C2 20
#define C3 54

#define OFF_XOUT 0
#define OFF_KAP  16
#define OFF_M    9437200
#define OFF_H    28311568

typedef unsigned long long u64;

__device__ float g_p1[NB * C1 * SP];
__device__ float g_p2[NB * C2 * SP];
__device__ float g_p3[NB * C3 * SP];
__device__ float g_xg[NB * NT * SP];
__device__ float g_w [NB * NT * SP];
__device__ float g_v [NB * NT * SP];
__device__ float g_kg [NB * NT * SP];
__device__ float g_m1 [NB * NT * SP];
__device__ float g_m2 [NB * NT * SP];
__device__ float g_h11[NB * NT * SP];
__device__ float g_hxy[NB * NT * SP];
__device__ float g_h22[NB * NT * SP];
__device__ float g_part[NB * 160];

__device__ __forceinline__ float sp10(float x) {
    float z = 10.0f * x;
    return (fmaxf(z, 0.0f) + log1pf(expf(-fabsf(z)))) * 0.1f;
}

__device__ __forceinline__ u64 pk2(float lo, float hi) {
    u64 r; asm("mov.b64 %0, {%1, %2};" : "=l"(r) : "f"(lo), "f"(hi)); return r;
}
__device__ __forceinline__ float2 upk(u64 v) {
    float2 r; asm("mov.b64 {%0, %1}, %2;" : "=f"(r.x), "=f"(r.y) : "l"(v)); return r;
}
__device__ __forceinline__ void fma2(u64& d, u64 a, u64 b) {
    asm("fma.rn.f32x2 %0, %1, %2, %0;" : "+l"(d) : "l"(a), "l"(b));
}

// ---------------------------------------------------------------------------
// 3x3 SAME conv. f32x2 packs TWO OUTPUT CHANNELS per accumulator.
// Thread: 1 output row, 8 px (two groups: 4*lane and 4*lane+128), 3 copairs.
// Block (32, YC) covers a full 256-wide row; grid (1, 256, NB).
// Tile: full row (258 cols) quartered: word = (c&3)*65 + (c>>2), 260/row.
// Stride-4 tap reads are lane-consecutive in each quarter: conflict-free.
// Weights pre-paired in smem as u64 (w[2p], w[2p+1]): uniform LDS.64.
// Per cin/thread: 12 LDS + 12 MOV + 27 LDS.64 + 216 fma2 -> 81% fma mix.
// ---------------------------------------------------------------------------
template <int CIN, bool RELU_IN, int YC, int COUT>
__global__ void __launch_bounds__(32 * YC, 2)
conv3x3_k(const float* __restrict__ in,
          const float* __restrict__ wts,
          float* __restrict__ out) {
    extern __shared__ float sh[];
    const int TS = 260;                      // words per tile row
    const int NP = YC * 3;                   // copairs total
    float* in_sh = sh;                       // CIN*3*TS floats
    u64*   w_sh  = (u64*)(sh + CIN * 3 * TS);// [CIN*9][NP] u64

    const int b  = blockIdx.z;
    const int y0 = blockIdx.y;               // output row
    const int nth = 32 * YC;
    const int tid = threadIdx.y * 32 + threadIdx.x;
    const int lane = threadIdx.x;

    // ---- tile: 3 src rows (y0-1..y0+1), 258 cols (gx = -1..256) ----
    const float* inb = in + (size_t)b * CIN * SP;
    for (int idx = tid; idx < CIN * 3 * 258; idx += nth) {
        int c  = idx % 258;
        int rr = (idx / 258) % 3;
        int ci = idx / 774;
        int gy = y0 - 1 + rr;
        int gx = c - 1;
        float v = 0.0f;
        if (gy >= 0 && gy < NYX && gx >= 0 && gx < NYX) {
            v = inb[ci * SP + gy * NYX + gx];
            if (RELU_IN) v = fmaxf(v, 0.0f);
        }
        in_sh[(ci * 3 + rr) * TS + (c & 3) * 65 + (c >> 2)] = v;
    }
    // ---- paired weights ----
    for (int idx = tid; idx < CIN * 9 * NP; idx += nth) {
        int p   = idx % NP;
        int tc  = idx / NP;
        int ci  = tc / 9;
        int tap = tc % 9;
        int c0 = 2 * p, c1 = 2 * p + 1;
        float lo = (c0 < COUT) ? wts[((size_t)c0 * CIN + ci) * 9 + tap] : 0.0f;
        float hi = (c1 < COUT) ? wts[((size_t)c1 * CIN + ci) * 9 + tap] : 0.0f;
        w_sh[idx] = pk2(lo, hi);
    }
    __syncthreads();

    const int pbase = threadIdx.y * 3;
    u64 acc[3][8];                           // [copair][group*4+px]
#pragma unroll
    for (int pp = 0; pp < 3; pp++)
#pragma unroll
        for (int q = 0; q < 8; q++) acc[pp][q] = 0ull;

    for (int cin = 0; cin < CIN; ++cin) {
#pragma unroll
        for (int sr = 0; sr < 3; ++sr) {     // src row; ky == sr
            const float* rp = in_sh + (cin * 3 + sr) * TS + lane;
            // group 0 taps: c = 4*lane + j
            float s0 = rp[0],  s1 = rp[65],  s2 = rp[130],
                  s3 = rp[195], s4 = rp[1],  s5 = rp[66];
            // group 1 taps: c = 4*lane + 128 + j  (+32 words per quarter)
            float q0 = rp[32], q1 = rp[97],  q2 = rp[162],
                  q3 = rp[227], q4 = rp[33], q5 = rp[98];
            u64 D[2][6];
            D[0][0] = pk2(s0, s0); D[0][1] = pk2(s1, s1); D[0][2] = pk2(s2, s2);
            D[0][3] = pk2(s3, s3); D[0][4] = pk2(s4, s4); D[0][5] = pk2(s5, s5);
            D[1][0] = pk2(q0, q0); D[1][1] = pk2(q1, q1); D[1][2] = pk2(q2, q2);
            D[1][3] = pk2(q3, q3); D[1][4] = pk2(q4, q4); D[1][5] = pk2(q5, q5);
            const u64* wr = w_sh + (size_t)(cin * 9 + sr * 3) * NP + pbase;
#pragma unroll
            for (int pp = 0; pp < 3; ++pp) {
                u64 W0 = wr[pp], W1 = wr[NP + pp], W2 = wr[2 * NP + pp];
#pragma unroll
                for (int g = 0; g < 2; ++g) {
#pragma unroll
                    for (int p = 0; p < 4; ++p) {
                        fma2(acc[pp][g * 4 + p], D[g][p],     W0);
                        fma2(acc[pp][g * 4 + p], D[g][p + 1], W1);
                        fma2(acc[pp][g * 4 + p], D[g][p + 2], W2);
                    }
                }
            }
        }
    }

    // ---- store: per copair, per group, two float4 stores (co, co+1) ----
#pragma unroll
    for (int pp = 0; pp < 3; ++pp) {
        int p = pbase + pp;
        int c0 = 2 * p, c1 = 2 * p + 1;
#pragma unroll
        for (int g = 0; g < 2; ++g) {
            int xb = lane * 4 + g * 128;
            float2 a0 = upk(acc[pp][g * 4 + 0]), a1 = upk(acc[pp][g * 4 + 1]),
                   a2 = upk(acc[pp][g * 4 + 2]), a3 = upk(acc[pp][g * 4 + 3]);
            if (c0 < COUT)
                *reinterpret_cast<float4*>(out + ((size_t)b * COUT + c0) * SP + (size_t)y0 * NYX + xb)
                    = make_float4(a0.x, a1.x, a2.x, a3.x);
            if (c1 < COUT)
                *reinterpret_cast<float4*>(out + ((size_t)b * COUT + c1) * SP + (size_t)y0 * NYX + xb)
                    = make_float4(a0.y, a1.y, a2.y, a3.y);
        }
    }
}

// ---------------------------------------------------------------------------
// Fused: kappa_r + m_r outputs AND kg/m1/m2 plane grids, via smem staging.
// ---------------------------------------------------------------------------
__global__ void epiA_scramble_k(float* __restrict__ out) {
    __shared__ float shk[2304], shm1[2304], shm2[2304];
    int b = blockIdx.y;
    int chunk = blockIdx.x;
    int L0 = chunk * 2304;
    int s0 = chunk * 256;
    const float* src = g_p3 + (size_t)b * C3 * SP;
    float* okap = out + OFF_KAP + (size_t)b * 9 * SP;
    float* om   = out + OFF_M   + (size_t)b * 18 * SP;
#pragma unroll
    for (int it = 0; it < 9; ++it) {
        int i = it * 256 + threadIdx.x;
        int L = L0 + i;
        float k  = sp10(src[L]);
        float m1 = src[9 * SP + L];
        float m2 = src[18 * SP + L];
        shk[i] = k; shm1[i] = m1; shm2[i] = m2;
        okap[L] = k;
        om[L] = m1;
        om[9 * SP + L] = m2;
    }
    __syncthreads();
#pragma unroll
    for (int it = 0; it < 9; ++it) {
        int i = it * 256 + threadIdx.x;
        int so = i & 255;
        int t = i >> 8;
        int si = 9 * so + t;
        size_t dst = ((size_t)b * 9 + t) * SP + s0 + so;
        g_kg[dst] = shk[si];
        g_m1[dst] = shm1[si];
        g_m2[dst] = shm2[si];
    }
}

// ---------------------------------------------------------------------------
__global__ void epiH_k(float* __restrict__ out) {
    int gid = blockIdx.x * blockDim.x + threadIdx.x;
    int b = gid >> 16;
    int s = gid & (SP - 1);
    const float* pb = g_p3 + (size_t)b * C3 * SP + s;
    float gm[NT], vx[NT], vy[NT];
#pragma unroll
    for (int t = 0; t < NT; t++) {
        gm[t] = sp10(pb[(size_t)(27 + t) * SP]);
        vx[t] = pb[(size_t)(36 + t) * SP];
        vy[t] = pb[(size_t)(45 + t) * SP];
    }
    const size_t PLANE = (size_t)SP * NT;
    size_t base = OFF_H + (size_t)b * 4 * PLANE + (size_t)s * NT;
    size_t pb2 = (size_t)b * NT * SP + s;
#pragma unroll
    for (int t = 0; t < NT; t++) {
        float h11 = gm[t] + vx[t] * vx[t];
        out[base + t] = h11;
        g_h11[pb2 + (size_t)t * SP] = h11;
    }
#pragma unroll
    for (int t = 0; t < NT; t++) {
        float xy = vx[t] * vy[t];
        out[base + PLANE + t]     = xy;
        out[base + 2 * PLANE + t] = xy;
        g_hxy[pb2 + (size_t)t * SP] = xy;
    }
#pragma unroll
    for (int t = 0; t < NT; t++) {
        float h22 = gm[t] + vy[t] * vy[t];
        out[base + 3 * PLANE + t] = h22;
        g_h22[pb2 + (size_t)t * SP] = h22;
    }
}

// ---------------------------------------------------------------------------
__global__ void transpose_k(const float* __restrict__ x) {
    __shared__ float tile[32][33];
    int b = blockIdx.z / NT, t = blockIdx.z % NT;
    const float* xb = x + ((size_t)b * NT + t) * SP;
    float* og = g_xg + ((size_t)b * NT + t) * SP;
    int Y0 = blockIdx.y * 32, X0 = blockIdx.x * 32;
#pragma unroll
    for (int k = 0; k < 4; k++) {
        int row = threadIdx.y + k * 8;
        tile[row][threadIdx.x] = xb[(size_t)(Y0 + row) * NYX + X0 + threadIdx.x];
    }
    __syncthreads();
#pragma unroll
    for (int k = 0; k < 4; k++) {
        int row = threadIdx.y + k * 8;
        og[(size_t)(X0 + row) * NYX + Y0 + threadIdx.x] = tile[threadIdx.x][row];
    }
}

// ---------------------------------------------------------------------------
__global__ void applyM_k(const float* __restrict__ u, float* __restrict__ og) {
    __shared__ float tile[10][36];
    int bt = blockIdx.z;
    int A0 = blockIdx.y * 8, C0 = blockIdx.x * 32;
    const float* ub = u + (size_t)bt * SP;
    int tid = threadIdx.y * 32 + threadIdx.x;
    for (int i = tid; i < 10 * 34; i += 256) {
        int rr = i / 34, cc = i % 34;
        int A = A0 - 1 + rr, C = C0 - 1 + cc;
        tile[rr][cc] = (A >= 0 && A < NYX && C >= 0 && C < NYX)
                       ? ub[(size_t)A * NYX + C] : 0.0f;
    }
    __syncthreads();
    int a = threadIdx.y, c = threadIdx.x;
    float u0 = tile[a + 1][c + 1];
    float xp = tile[a + 2][c + 1], xm = tile[a][c + 1];
    float yp = tile[a + 1][c + 2], ym = tile[a + 1][c];
    float pp = tile[a + 2][c + 2], pm = tile[a + 2][c];
    float mp = tile[a][c + 2],     mm = tile[a][c];
    float dx  = 0.5f * (xp - xm);
    float dy  = 0.5f * (yp - ym);
    float dxx = xp - 2.0f * u0 + xm;
    float dyy = yp - 2.0f * u0 + ym;
    float dxy = 0.25f * (pp - pm - mp + mm);

    int s = (A0 + a) * NYX + (C0 + c);
    size_t pl = (size_t)bt * SP + s;
    float kap = g_kg[pl];
    float m1  = g_m1[pl];
    float m2  = g_m2[pl];
    float h11 = g_h11[pl];
    float hxy = g_hxy[pl];
    float h22 = g_h22[pl];

    float r = u0 + kap * kap * u0 + m1 * dx + m2 * dy
            - (h11 * dxx + 2.0f * hxy * dxy + h22 * dyy);
    og[pl] = r;
}

// ---------------------------------------------------------------------------
__global__ void qx_reduce_k() {
    __shared__ float sm[256];
    int b = blockIdx.y;
    size_t base = (size_t)blockIdx.x * 4096;
    const float* xb = g_xg + (size_t)b * NT * SP;
    const float* wb = g_w  + (size_t)b * NT * SP;
    const float* vb = g_v  + (size_t)b * NT * SP;
    float sum = 0.0f;
    for (int i = threadIdx.x; i < 4096; i += 256) {
        size_t e = base + i;
        int t = (int)(e >> 16);
        int s = (int)(e & (SP - 1));
        float q;
        if (t == 0)       q = vb[s] - wb[SP + s];
        else if (t == 8)  q = -wb[7 * SP + s] + vb[8 * (size_t)SP + s];
        else              q = -wb[(size_t)(t - 1) * SP + s] + vb[e] + xb[e]
                              - wb[(size_t)(t + 1) * SP + s];
        sum += xb[e] * q;
    }
    sm[threadIdx.x] = sum;
    __syncthreads();
    for (int st = 128; st > 0; st >>= 1) {
        if (threadIdx.x < st) sm[threadIdx.x] += sm[threadIdx.x + st];
        __syncthreads();
    }
    if (threadIdx.x == 0) g_part[b * 160 + blockIdx.x] = sm[0];
}

__global__ void final_reduce_k(float* __restrict__ out) {
    int b = threadIdx.x;
    if (b < NB) {
        float s = 0.0f;
        for (int i = 0; i < 144; i++) s += g_part[b * 160 + i];
        out[OFF_XOUT + b] = s;
    }
}

// ---------------------------------------------------------------------------
extern "C" void kernel_launch(void* const* d_in, const int* in_sizes, int n_in,
                              void* d_out, int out_size) {
    const float* x  = (const float*)d_in[0];
    const float* w1 = (const float*)d_in[4];
    const float* w2 = (const float*)d_in[5];
    const float* w3 = (const float*)d_in[6];
    float* out = (float*)d_out;

    float *p1, *p2, *p3, *xg, *wg, *vg;
    cudaGetSymbolAddress((void**)&p1, g_p1);
    cudaGetSymbolAddress((void**)&p2, g_p2);
    cudaGetSymbolAddress((void**)&p3, g_p3);
    cudaGetSymbolAddress((void**)&xg, g_xg);
    cudaGetSymbolAddress((void**)&wg, g_w);
    cudaGetSymbolAddress((void**)&vg, g_v);

    // smem: tile CIN*3*260*4 + weights CIN*9*NP*8
    const int smem1 = 9  * 3 * 260 * 4 + 9  * 9 * 6  * 8;   // 31,968
    const int smem2 = 10 * 3 * 260 * 4 + 10 * 9 * 12 * 8;   // 39,840
    const int smem3 = 20 * 3 * 260 * 4 + 20 * 9 * 27 * 8;   // 101,280
    cudaFuncSetAttribute((const void*)conv3x3_k<9,  true,  2, C1>, cudaFuncAttributeMaxDynamicSharedMemorySize, smem1);
    cudaFuncSetAttribute((const void*)conv3x3_k<10, true,  4, C2>, cudaFuncAttributeMaxDynamicSharedMemorySize, smem2);
    cudaFuncSetAttribute((const void*)conv3x3_k<20, false, 9, C3>, cudaFuncAttributeMaxDynamicSharedMemorySize, smem3);

    // 1: transpose (independent of convs)
    transpose_k<<<dim3(8, 8, NB * NT), dim3(32, 8)>>>(x);
    // 2,3,4: conv chain — conv3 in the profiled launch slot
    conv3x3_k<9,  true,  2, C1><<<dim3(1, 256, NB), dim3(32, 2), smem1>>>(x,  w1, p1);
    conv3x3_k<10, true,  4, C2><<<dim3(1, 256, NB), dim3(32, 4), smem2>>>(p1, w2, p2);
    conv3x3_k<20, false, 9, C3><<<dim3(1, 256, NB), dim3(32, 9), smem3>>>(p2, w3, p3);

    // epilogues
    epiH_k<<<(NB * SP) / 256, 256>>>(out);
    epiA_scramble_k<<<dim3(256, NB), 256>>>(out);

    // PDE pipeline
    applyM_k<<<dim3(8, 32, NB * NT), dim3(32, 8)>>>(xg, wg);
    applyM_k<<<dim3(8, 32, NB * NT), dim3(32, 8)>>>(wg, vg);
    qx_reduce_k<<<dim3(144, NB), 256>>>();
    final_reduce_k<<<1, 32>>>(out);
}

// round 8
// speedup vs baseline: 1.5599x; 1.1745x over previous
#include <cuda_runtime.h>
#include <cuda_bf16.h>
#include <cstdint>

#define NB 16
#define NT 9
#define NYX 256
#define SP 65536
#define C1 10
#define C2 20
#define C3 54

#define OFF_XOUT 0
#define OFF_KAP  16
#define OFF_M    9437200
#define OFF_H    28311568

typedef unsigned long long u64;

__device__ float g_p1[NB * C1 * SP];
__device__ float g_p2[NB * C2 * SP];
__device__ float g_p3[NB * C3 * SP];
__device__ float g_xg[NB * NT * SP];
__device__ float g_w [NB * NT * SP];
__device__ float g_v [NB * NT * SP];
__device__ float g_kg [NB * NT * SP];
__device__ float g_m1 [NB * NT * SP];
__device__ float g_m2 [NB * NT * SP];
__device__ float g_h11[NB * NT * SP];
__device__ float g_hxy[NB * NT * SP];
__device__ float g_h22[NB * NT * SP];
__device__ float g_part[NB * 160];
// conv3 weight fragments: [mtile(4)][kstep(23)][lane(32)] x {hi float4, lo float4}
__device__ float4 g_wfrag[4 * 23 * 32 * 2];

__device__ __forceinline__ float sp10(float x) {
    float z = 10.0f * x;
    return (fmaxf(z, 0.0f) + log1pf(expf(-fabsf(z)))) * 0.1f;
}

__device__ __forceinline__ u64 pk2(float lo, float hi) {
    u64 r; asm("mov.b64 %0, {%1, %2};" : "=l"(r) : "f"(lo), "f"(hi)); return r;
}
__device__ __forceinline__ float2 upk(u64 v) {
    float2 r; asm("mov.b64 {%0, %1}, %2;" : "=f"(r.x), "=f"(r.y) : "l"(v)); return r;
}
__device__ __forceinline__ void fma2(u64& d, u64 a, u64 b) {
    asm("fma.rn.f32x2 %0, %1, %2, %0;" : "+l"(d) : "l"(a), "l"(b));
}
__device__ __forceinline__ float to_tf32(float x) {
    uint32_t r; asm("cvt.rna.tf32.f32 %0, %1;" : "=r"(r) : "f"(x));
    return __uint_as_float(r);
}
__device__ __forceinline__ void mma_tf32(float* d, const uint32_t* a, const uint32_t* b) {
    asm("mma.sync.aligned.m16n8k8.row.col.f32.tf32.tf32.f32 "
        "{%0,%1,%2,%3}, {%4,%5,%6,%7}, {%8,%9}, {%0,%1,%2,%3};"
        : "+f"(d[0]), "+f"(d[1]), "+f"(d[2]), "+f"(d[3])
        : "r"(a[0]), "r"(a[1]), "r"(a[2]), "r"(a[3]), "r"(b[0]), "r"(b[1]));
}

// ---------------------------------------------------------------------------
// Prep: conv3 weights -> fragment-ordered hi/lo TF32 split.
// thread idx -> (mtile, kstep, lane). a_i layout of m16n8k8.row:
// a0(g,tig) a1(g+8,tig) a2(g,tig+4) a3(g+8,tig+4); row=cout, col=k.
// ---------------------------------------------------------------------------
__global__ void prep_w3_k(const float* __restrict__ w3) {
    int idx = blockIdx.x * blockDim.x + threadIdx.x;
    if (idx >= 4 * 23 * 32) return;
    int lane  = idx & 31;
    int ks    = (idx >> 5) % 23;
    int mtile = idx / (23 * 32);
    int g = lane >> 2, tig = lane & 3;
    float hi[4], lo[4];
#pragma unroll
    for (int i = 0; i < 4; i++) {
        int row = mtile * 16 + g + (i & 1) * 8;
        int k   = ks * 8 + tig + (i >> 1) * 4;
        float w = (row < C3 && k < 180) ? w3[row * 180 + k] : 0.0f;
        float h = to_tf32(w);
        hi[i] = h;
        lo[i] = to_tf32(w - h);
    }
    int base = ((mtile * 23 + ks) * 32 + lane) * 2;
    g_wfrag[base]     = make_float4(hi[0], hi[1], hi[2], hi[3]);
    g_wfrag[base + 1] = make_float4(lo[0], lo[1], lo[2], lo[3]);
}

// ---------------------------------------------------------------------------
// conv3 via tensor cores (implicit GEMM, tf32 3-pass).
// Block (32,8): 8 warps, one output row y0 (256 px), all 54 couts, one batch.
// K = 180 (20 cin x 9 taps) padded to 184 = 23 k-steps of 8.
// smem: tile [61 rows][258] (rows 0..59 = (ci,ky); row 60 = zeros) + koff[184].
// Warp w: n-tiles 4w..4w+3 (8 px each). acc[4 mtiles][4 ntiles][4].
// ---------------------------------------------------------------------------
__global__ void __launch_bounds__(256, 2)
conv3_mma_k(const float* __restrict__ in, float* __restrict__ out) {
    extern __shared__ float sh[];
    const int TS = 258;
    float* tile = sh;                       // 61*258 floats
    int*   koff = (int*)(sh + 61 * TS);     // 184 ints

    const int b  = blockIdx.z;
    const int y0 = blockIdx.y;
    const int tid = threadIdx.y * 32 + threadIdx.x;

    const float* inb = in + (size_t)b * C2 * SP;
    for (int idx = tid; idx < C2 * 3 * 258; idx += 256) {
        int c  = idx % 258;
        int rr = (idx / 258) % 3;
        int ci = idx / 774;
        int gy = y0 - 1 + rr;
        int gx = c - 1;
        float v = 0.0f;
        if (gy >= 0 && gy < NYX && gx >= 0 && gx < NYX)
            v = inb[ci * SP + gy * NYX + gx];
        tile[(ci * 3 + rr) * TS + c] = v;
    }
    for (int i = tid; i < 258; i += 256) tile[60 * TS + i] = 0.0f;
    for (int k = tid; k < 184; k += 256) {
        if (k < 180) {
            int ci = k / 9, r = k % 9;
            koff[k] = (ci * 3 + r / 3) * TS + (r % 3);
        } else {
            koff[k] = 60 * TS;
        }
    }
    __syncthreads();

    const int warp = threadIdx.y;
    const int lane = threadIdx.x;
    const int g = lane >> 2, tig = lane & 3;
    const int nbase = warp * 32;

    float acc[4][4][4];
#pragma unroll
    for (int m = 0; m < 4; m++)
#pragma unroll
        for (int n = 0; n < 4; n++)
#pragma unroll
            for (int q = 0; q < 4; q++) acc[m][n][q] = 0.0f;

    for (int ks = 0; ks < 23; ks++) {
        // ---- B fragments: X[k][n], hi/lo split ----
        uint32_t bhi[4][2], blo[4][2];
        int o0 = koff[ks * 8 + tig];
        int o1 = koff[ks * 8 + tig + 4];
#pragma unroll
        for (int nt = 0; nt < 4; nt++) {
            int n = nbase + nt * 8 + g;
            float x0 = tile[o0 + n];
            float x1 = tile[o1 + n];
            float h0 = to_tf32(x0), h1 = to_tf32(x1);
            bhi[nt][0] = __float_as_uint(h0);
            bhi[nt][1] = __float_as_uint(h1);
            blo[nt][0] = __float_as_uint(to_tf32(x0 - h0));
            blo[nt][1] = __float_as_uint(to_tf32(x1 - h1));
        }
        // ---- A fragments + MMAs ----
#pragma unroll
        for (int mt = 0; mt < 4; mt++) {
            int base = ((mt * 23 + ks) * 32 + lane) * 2;
            float4 ah = g_wfrag[base];
            float4 al = g_wfrag[base + 1];
            uint32_t ahi[4] = { __float_as_uint(ah.x), __float_as_uint(ah.y),
                                __float_as_uint(ah.z), __float_as_uint(ah.w) };
            uint32_t alo[4] = { __float_as_uint(al.x), __float_as_uint(al.y),
                                __float_as_uint(al.z), __float_as_uint(al.w) };
#pragma unroll
            for (int nt = 0; nt < 4; nt++) {
                mma_tf32(acc[mt][nt], ahi, bhi[nt]);
                mma_tf32(acc[mt][nt], ahi, blo[nt]);
                mma_tf32(acc[mt][nt], alo, bhi[nt]);
            }
        }
    }

    // ---- store: d0,d1 -> (co = mt*16+g, px = nbase+nt*8+2*tig), d2,d3 -> co+8
#pragma unroll
    for (int mt = 0; mt < 4; mt++) {
        int co0 = mt * 16 + g;
#pragma unroll
        for (int nt = 0; nt < 4; nt++) {
            int px = nbase + nt * 8 + 2 * tig;
            float* op = out + ((size_t)b * C3 + co0) * SP + (size_t)y0 * NYX + px;
            if (co0 < C3)
                *reinterpret_cast<float2*>(op) = make_float2(acc[mt][nt][0], acc[mt][nt][1]);
            if (co0 + 8 < C3)
                *reinterpret_cast<float2*>(op + (size_t)8 * SP) = make_float2(acc[mt][nt][2], acc[mt][nt][3]);
        }
    }
}

// ---------------------------------------------------------------------------
// Scalar conv (R7 path) for conv1 / conv2.
// ---------------------------------------------------------------------------
template <int CIN, bool RELU_IN, int YC, int COUT>
__global__ void __launch_bounds__(32 * YC, 2)
conv3x3_k(const float* __restrict__ in,
          const float* __restrict__ wts,
          float* __restrict__ out) {
    extern __shared__ float sh[];
    const int TS = 260;
    const int NP = YC * 3;
    float* in_sh = sh;
    u64*   w_sh  = (u64*)(sh + CIN * 3 * TS);

    const int b  = blockIdx.z;
    const int y0 = blockIdx.y;
    const int nth = 32 * YC;
    const int tid = threadIdx.y * 32 + threadIdx.x;
    const int lane = threadIdx.x;

    const float* inb = in + (size_t)b * CIN * SP;
    for (int idx = tid; idx < CIN * 3 * 258; idx += nth) {
        int c  = idx % 258;
        int rr = (idx / 258) % 3;
        int ci = idx / 774;
        int gy = y0 - 1 + rr;
        int gx = c - 1;
        float v = 0.0f;
        if (gy >= 0 && gy < NYX && gx >= 0 && gx < NYX) {
            v = inb[ci * SP + gy * NYX + gx];
            if (RELU_IN) v = fmaxf(v, 0.0f);
        }
        in_sh[(ci * 3 + rr) * TS + (c & 3) * 65 + (c >> 2)] = v;
    }
    for (int idx = tid; idx < CIN * 9 * NP; idx += nth) {
        int p   = idx % NP;
        int tc  = idx / NP;
        int ci  = tc / 9;
        int tap = tc % 9;
        int c0 = 2 * p, c1 = 2 * p + 1;
        float lo = (c0 < COUT) ? wts[((size_t)c0 * CIN + ci) * 9 + tap] : 0.0f;
        float hi = (c1 < COUT) ? wts[((size_t)c1 * CIN + ci) * 9 + tap] : 0.0f;
        w_sh[idx] = pk2(lo, hi);
    }
    __syncthreads();

    const int pbase = threadIdx.y * 3;
    u64 acc[3][8];
#pragma unroll
    for (int pp = 0; pp < 3; pp++)
#pragma unroll
        for (int q = 0; q < 8; q++) acc[pp][q] = 0ull;

    for (int cin = 0; cin < CIN; ++cin) {
#pragma unroll
        for (int sr = 0; sr < 3; ++sr) {
            const float* rp = in_sh + (cin * 3 + sr) * TS + lane;
            float s0 = rp[0],  s1 = rp[65],  s2 = rp[130],
                  s3 = rp[195], s4 = rp[1],  s5 = rp[66];
            float q0 = rp[32], q1 = rp[97],  q2 = rp[162],
                  q3 = rp[227], q4 = rp[33], q5 = rp[98];
            u64 D[2][6];
            D[0][0] = pk2(s0, s0); D[0][1] = pk2(s1, s1); D[0][2] = pk2(s2, s2);
            D[0][3] = pk2(s3, s3); D[0][4] = pk2(s4, s4); D[0][5] = pk2(s5, s5);
            D[1][0] = pk2(q0, q0); D[1][1] = pk2(q1, q1); D[1][2] = pk2(q2, q2);
            D[1][3] = pk2(q3, q3); D[1][4] = pk2(q4, q4); D[1][5] = pk2(q5, q5);
            const u64* wr = w_sh + (size_t)(cin * 9 + sr * 3) * NP + pbase;
#pragma unroll
            for (int pp = 0; pp < 3; ++pp) {
                u64 W0 = wr[pp], W1 = wr[NP + pp], W2 = wr[2 * NP + pp];
#pragma unroll
                for (int gg = 0; gg < 2; ++gg) {
#pragma unroll
                    for (int p = 0; p < 4; ++p) {
                        fma2(acc[pp][gg * 4 + p], D[gg][p],     W0);
                        fma2(acc[pp][gg * 4 + p], D[gg][p + 1], W1);
                        fma2(acc[pp][gg * 4 + p], D[gg][p + 2], W2);
                    }
                }
            }
        }
    }

#pragma unroll
    for (int pp = 0; pp < 3; ++pp) {
        int p = pbase + pp;
        int c0 = 2 * p, c1 = 2 * p + 1;
#pragma unroll
        for (int gg = 0; gg < 2; ++gg) {
            int xb = lane * 4 + gg * 128;
            float2 a0 = upk(acc[pp][gg * 4 + 0]), a1 = upk(acc[pp][gg * 4 + 1]),
                   a2 = upk(acc[pp][gg * 4 + 2]), a3 = upk(acc[pp][gg * 4 + 3]);
            if (c0 < COUT)
                *reinterpret_cast<float4*>(out + ((size_t)b * COUT + c0) * SP + (size_t)y0 * NYX + xb)
                    = make_float4(a0.x, a1.x, a2.x, a3.x);
            if (c1 < COUT)
                *reinterpret_cast<float4*>(out + ((size_t)b * COUT + c1) * SP + (size_t)y0 * NYX + xb)
                    = make_float4(a0.y, a1.y, a2.y, a3.y);
        }
    }
}

// ---------------------------------------------------------------------------
__global__ void epiA_scramble_k(float* __restrict__ out) {
    __shared__ float shk[2304], shm1[2304], shm2[2304];
    int b = blockIdx.y;
    int chunk = blockIdx.x;
    int L0 = chunk * 2304;
    int s0 = chunk * 256;
    const float* src = g_p3 + (size_t)b * C3 * SP;
    float* okap = out + OFF_KAP + (size_t)b * 9 * SP;
    float* om   = out + OFF_M   + (size_t)b * 18 * SP;
#pragma unroll
    for (int it = 0; it < 9; ++it) {
        int i = it * 256 + threadIdx.x;
        int L = L0 + i;
        float k  = sp10(src[L]);
        float m1 = src[9 * SP + L];
        float m2 = src[18 * SP + L];
        shk[i] = k; shm1[i] = m1; shm2[i] = m2;
        okap[L] = k;
        om[L] = m1;
        om[9 * SP + L] = m2;
    }
    __syncthreads();
#pragma unroll
    for (int it = 0; it < 9; ++it) {
        int i = it * 256 + threadIdx.x;
        int so = i & 255;
        int t = i >> 8;
        int si = 9 * so + t;
        size_t dst = ((size_t)b * 9 + t) * SP + s0 + so;
        g_kg[dst] = shk[si];
        g_m1[dst] = shm1[si];
        g_m2[dst] = shm2[si];
    }
}

// ---------------------------------------------------------------------------
__global__ void epiH_k(float* __restrict__ out) {
    int gid = blockIdx.x * blockDim.x + threadIdx.x;
    int b = gid >> 16;
    int s = gid & (SP - 1);
    const float* pb = g_p3 + (size_t)b * C3 * SP + s;
    float gm[NT], vx[NT], vy[NT];
#pragma unroll
    for (int t = 0; t < NT; t++) {
        gm[t] = sp10(pb[(size_t)(27 + t) * SP]);
        vx[t] = pb[(size_t)(36 + t) * SP];
        vy[t] = pb[(size_t)(45 + t) * SP];
    }
    const size_t PLANE = (size_t)SP * NT;
    size_t base = OFF_H + (size_t)b * 4 * PLANE + (size_t)s * NT;
    size_t pb2 = (size_t)b * NT * SP + s;
#pragma unroll
    for (int t = 0; t < NT; t++) {
        float h11 = gm[t] + vx[t] * vx[t];
        out[base + t] = h11;
        g_h11[pb2 + (size_t)t * SP] = h11;
    }
#pragma unroll
    for (int t = 0; t < NT; t++) {
        float xy = vx[t] * vy[t];
        out[base + PLANE + t]     = xy;
        out[base + 2 * PLANE + t] = xy;
        g_hxy[pb2 + (size_t)t * SP] = xy;
    }
#pragma unroll
    for (int t = 0; t < NT; t++) {
        float h22 = gm[t] + vy[t] * vy[t];
        out[base + 3 * PLANE + t] = h22;
        g_h22[pb2 + (size_t)t * SP] = h22;
    }
}

// ---------------------------------------------------------------------------
__global__ void transpose_k(const float* __restrict__ x) {
    __shared__ float tile[32][33];
    int b = blockIdx.z / NT, t = blockIdx.z % NT;
    const float* xb = x + ((size_t)b * NT + t) * SP;
    float* og = g_xg + ((size_t)b * NT + t) * SP;
    int Y0 = blockIdx.y * 32, X0 = blockIdx.x * 32;
#pragma unroll
    for (int k = 0; k < 4; k++) {
        int row = threadIdx.y + k * 8;
        tile[row][threadIdx.x] = xb[(size_t)(Y0 + row) * NYX + X0 + threadIdx.x];
    }
    __syncthreads();
#pragma unroll
    for (int k = 0; k < 4; k++) {
        int row = threadIdx.y + k * 8;
        og[(size_t)(X0 + row) * NYX + Y0 + threadIdx.x] = tile[threadIdx.x][row];
    }
}

// ---------------------------------------------------------------------------
__global__ void applyM_k(const float* __restrict__ u, float* __restrict__ og) {
    __shared__ float tile[10][36];
    int bt = blockIdx.z;
    int A0 = blockIdx.y * 8, C0 = blockIdx.x * 32;
    const float* ub = u + (size_t)bt * SP;
    int tid = threadIdx.y * 32 + threadIdx.x;
    for (int i = tid; i < 10 * 34; i += 256) {
        int rr = i / 34, cc = i % 34;
        int A = A0 - 1 + rr, C = C0 - 1 + cc;
        tile[rr][cc] = (A >= 0 && A < NYX && C >= 0 && C < NYX)
                       ? ub[(size_t)A * NYX + C] : 0.0f;
    }
    __syncthreads();
    int a = threadIdx.y, c = threadIdx.x;
    float u0 = tile[a + 1][c + 1];
    float xp = tile[a + 2][c + 1], xm = tile[a][c + 1];
    float yp = tile[a + 1][c + 2], ym = tile[a + 1][c];
    float pp = tile[a + 2][c + 2], pm = tile[a + 2][c];
    float mp = tile[a][c + 2],     mm = tile[a][c];
    float dx  = 0.5f * (xp - xm);
    float dy  = 0.5f * (yp - ym);
    float dxx = xp - 2.0f * u0 + xm;
    float dyy = yp - 2.0f * u0 + ym;
    float dxy = 0.25f * (pp - pm - mp + mm);

    int s = (A0 + a) * NYX + (C0 + c);
    size_t pl = (size_t)bt * SP + s;
    float kap = g_kg[pl];
    float m1  = g_m1[pl];
    float m2  = g_m2[pl];
    float h11 = g_h11[pl];
    float hxy = g_hxy[pl];
    float h22 = g_h22[pl];

    float r = u0 + kap * kap * u0 + m1 * dx + m2 * dy
            - (h11 * dxx + 2.0f * hxy * dxy + h22 * dyy);
    og[pl] = r;
}

// ---------------------------------------------------------------------------
__global__ void qx_reduce_k() {
    __shared__ float sm[256];
    int b = blockIdx.y;
    size_t base = (size_t)blockIdx.x * 4096;
    const float* xb = g_xg + (size_t)b * NT * SP;
    const float* wb = g_w  + (size_t)b * NT * SP;
    const float* vb = g_v  + (size_t)b * NT * SP;
    float sum = 0.0f;
    for (int i = threadIdx.x; i < 4096; i += 256) {
        size_t e = base + i;
        int t = (int)(e >> 16);
        int s = (int)(e & (SP - 1));
        float q;
        if (t == 0)       q = vb[s] - wb[SP + s];
        else if (t == 8)  q = -wb[7 * SP + s] + vb[8 * (size_t)SP + s];
        else              q = -wb[(size_t)(t - 1) * SP + s] + vb[e] + xb[e]
                              - wb[(size_t)(t + 1) * SP + s];
        sum += xb[e] * q;
    }
    sm[threadIdx.x] = sum;
    __syncthreads();
    for (int st = 128; st > 0; st >>= 1) {
        if (threadIdx.x < st) sm[threadIdx.x] += sm[threadIdx.x + st];
        __syncthreads();
    }
    if (threadIdx.x == 0) g_part[b * 160 + blockIdx.x] = sm[0];
}

__global__ void final_reduce_k(float* __restrict__ out) {
    int b = threadIdx.x;
    if (b < NB) {
        float s = 0.0f;
        for (int i = 0; i < 144; i++) s += g_part[b * 160 + i];
        out[OFF_XOUT + b] = s;
    }
}

// ---------------------------------------------------------------------------
extern "C" void kernel_launch(void* const* d_in, const int* in_sizes, int n_in,
                              void* d_out, int out_size) {
    const float* x  = (const float*)d_in[0];
    const float* w1 = (const float*)d_in[4];
    const float* w2 = (const float*)d_in[5];
    const float* w3 = (const float*)d_in[6];
    float* out = (float*)d_out;

    float *p1, *p2, *p3, *xg, *wg, *vg;
    cudaGetSymbolAddress((void**)&p1, g_p1);
    cudaGetSymbolAddress((void**)&p2, g_p2);
    cudaGetSymbolAddress((void**)&p3, g_p3);
    cudaGetSymbolAddress((void**)&xg, g_xg);
    cudaGetSymbolAddress((void**)&wg, g_w);
    cudaGetSymbolAddress((void**)&vg, g_v);

    const int smem1 = 9  * 3 * 260 * 4 + 9  * 9 * 6  * 8;   // 31,968
    const int smem2 = 10 * 3 * 260 * 4 + 10 * 9 * 12 * 8;   // 39,840
    const int smem3m = 61 * 258 * 4 + 184 * 4;               // 63,688
    cudaFuncSetAttribute((const void*)conv3x3_k<9,  true,  2, C1>, cudaFuncAttributeMaxDynamicSharedMemorySize, smem1);
    cudaFuncSetAttribute((const void*)conv3x3_k<10, true,  4, C2>, cudaFuncAttributeMaxDynamicSharedMemorySize, smem2);
    cudaFuncSetAttribute((const void*)conv3_mma_k, cudaFuncAttributeMaxDynamicSharedMemorySize, smem3m);

    // 1: weight prep (tiny)
    prep_w3_k<<<12, 256>>>(w3);
    // 2,3,4: conv chain — conv3 (tensor) in the profiled launch slot
    conv3x3_k<9,  true,  2, C1><<<dim3(1, 256, NB), dim3(32, 2), smem1>>>(x,  w1, p1);
    conv3x3_k<10, true,  4, C2><<<dim3(1, 256, NB), dim3(32, 4), smem2>>>(p1, w2, p2);
    conv3_mma_k<<<dim3(1, 256, NB), dim3(32, 8), smem3m>>>(p2, p3);

    // independent of convs
    transpose_k<<<dim3(8, 8, NB * NT), dim3(32, 8)>>>(x);

    // epilogues
    epiH_k<<<(NB * SP) / 256, 256>>>(out);
    epiA_scramble_k<<<dim3(256, NB), 256>>>(out);

    // PDE pipeline
    applyM_k<<<dim3(8, 32, NB * NT), dim3(32, 8)>>>(xg, wg);
    applyM_k<<<dim3(8, 32, NB * NT), dim3(32, 8)>>>(wg, vg);
    qx_reduce_k<<<dim3(144, NB), 256>>>();
    final_reduce_k<<<1, 32>>>(out);
}